// round 11
// baseline (speedup 1.0000x reference)
#include <cuda_runtime.h>
#include <math.h>

// Problem constants
constexpr int kB = 64, kN = 1024, kF = 16, kD = 64, kK = 20;
constexpr int kM = kB * kN;              // 65536 rows
constexpr float kEps = 1e-5f, kSlope = 0.2f;

// ---------------- scratch (device globals: allocation-free) ----------------
__device__ float  g_h[(size_t)kM * kD];      // 16 MB
__device__ float  g_out1[(size_t)kM * kD];   // 16 MB
__device__ float2 g_esi2[kM];                // {e^si, e^{0.2 si}}
__device__ float2 g_esj2[kM];                // {e^sj, e^{0.2 sj}}
__device__ float  g_emi[kN];
__device__ float  g_emj[kN];
__device__ float  g_cos[(size_t)kN * kN];    // 4 MB
__device__ int    g_idx[kN * kK];
__device__ float2 g_alpha[(size_t)kM * kK];  // 10.5 MB packed (e, id) UNnormalized
__device__ double g_sum1[kD], g_ssq1[kD], g_sum2[kD], g_ssq2[kD];
__device__ int    g_bar[2];                  // grid barrier counters

// ---------------- kernel 1: cosine Gram + norms + emb-att dots + zeroing ----
__global__ void k_cos(const float* __restrict__ emb,
                      const float* __restrict__ aei,
                      const float* __restrict__ aej) {
    __shared__ float As[kD][65];
    __shared__ float Bs[kD][65];
    __shared__ float rnA[64], rnB[64];
    int t = threadIdx.x;
    int bn = blockIdx.y * 64, bm = blockIdx.x * 64;
    if (blockIdx.x == 0 && blockIdx.y == 0) {
        if (t < kD) { g_sum1[t] = 0.0; g_ssq1[t] = 0.0; g_sum2[t] = 0.0; g_ssq2[t] = 0.0; }
        if (t >= 64 && t < 66) g_bar[t - 64] = 0;
    }
    for (int idx = t; idx < 64 * 64; idx += 256) {
        int r = idx >> 6, k = idx & 63;
        As[k][r] = emb[(size_t)(bn + r) * kD + k];
        Bs[k][r] = emb[(size_t)(bm + r) * kD + k];
    }
    __syncthreads();
    if (t < 64) {
        float s = 0.f;
        for (int k = 0; k < 64; k++) { float v = As[k][t]; s += v * v; }
        rnA[t] = 1.0f / sqrtf(s);
    } else if (t < 128) {
        int r = t - 64;
        float s = 0.f;
        for (int k = 0; k < 64; k++) { float v = Bs[k][r]; s += v * v; }
        rnB[r] = 1.0f / sqrtf(s);
    } else if (blockIdx.x == 0) {
        int r = (t - 128) & 63;
        const float* av = (t < 192) ? aei : aej;
        float s = 0.f;
        for (int k = 0; k < 64; k++) s += As[k][r] * av[k];
        if (t < 192) g_emi[bn + r] = s; else g_emj[bn + r] = s;
    }
    int tx = t & 15, ty = t >> 4;
    float acc[4][4] = {};
#pragma unroll 4
    for (int k = 0; k < 64; k++) {
        float a[4], b[4];
#pragma unroll
        for (int i = 0; i < 4; i++) { a[i] = As[k][ty * 4 + i]; b[i] = Bs[k][tx * 4 + i]; }
#pragma unroll
        for (int i = 0; i < 4; i++)
#pragma unroll
            for (int j = 0; j < 4; j++) acc[i][j] += a[i] * b[j];
    }
    __syncthreads();
#pragma unroll
    for (int i = 0; i < 4; i++) {
        int r = bn + ty * 4 + i;
        float rn = rnA[ty * 4 + i];
#pragma unroll
        for (int j = 0; j < 4; j++) {
            int c = bm + tx * 4 + j;
            g_cos[(size_t)r * kN + c] = acc[i][j] * rn * rnB[tx * 4 + j];
        }
    }
}

// ---------------- kernel 2: h = data @ lin_w^T + exp tables -----------------
__global__ void k_h(const float* __restrict__ data, const float* __restrict__ lin_w,
                    const float* __restrict__ att_i, const float* __restrict__ att_j) {
    __shared__ float lw[kF][kD];
    for (int idx = threadIdx.x; idx < kF * kD; idx += blockDim.x) {
        int f = idx >> 6, d = idx & 63;
        lw[f][d] = lin_w[d * kF + f];
    }
    __syncthreads();
    int lane = threadIdx.x & 31;
    int gw = (blockIdx.x * blockDim.x + threadIdx.x) >> 5;
    int nw = (gridDim.x * blockDim.x) >> 5;
    float ai0 = att_i[lane], ai1 = att_i[lane + 32];
    float aj0 = att_j[lane], aj1 = att_j[lane + 32];
    for (int r = gw; r < kM; r += nw) {
        const float4* dp = reinterpret_cast<const float4*>(data + (size_t)r * kF);
        float4 q0 = dp[0], q1 = dp[1], q2 = dp[2], q3 = dp[3];
        float df[16] = {q0.x, q0.y, q0.z, q0.w, q1.x, q1.y, q1.z, q1.w,
                        q2.x, q2.y, q2.z, q2.w, q3.x, q3.y, q3.z, q3.w};
        float h0 = 0.f, h1 = 0.f;
#pragma unroll
        for (int f = 0; f < 16; f++) {
            h0 += df[f] * lw[f][lane];
            h1 += df[f] * lw[f][lane + 32];
        }
        g_h[(size_t)r * kD + lane] = h0;
        g_h[(size_t)r * kD + lane + 32] = h1;
        float si = h0 * ai0 + h1 * ai1;
        float sj = h0 * aj0 + h1 * aj1;
#pragma unroll
        for (int o = 16; o; o >>= 1) {
            si += __shfl_xor_sync(0xffffffffu, si, o);
            sj += __shfl_xor_sync(0xffffffffu, sj, o);
        }
        if (lane == 0) {
            int n = r & (kN - 1);
            float siv = si + g_emi[n], sjv = sj + g_emj[n];
            g_esi2[r] = make_float2(expf(siv), expf(0.2f * siv));
            g_esj2[r] = make_float2(expf(sjv), expf(0.2f * sjv));
        }
    }
}

// ---------------- kernel 3: exact top-20 via 4-pass 8-bit radix select ------
__global__ void k_topk() {
    __shared__ unsigned sv[kN];
    __shared__ int hist[256];
    __shared__ int suf[256];
    __shared__ int tie[kN];
    __shared__ int s_digit, s_above, s_need, s_cntA, s_cntT, s_sel;
    __shared__ int wmin[8];
    int n = blockIdx.x, t = threadIdx.x;
    int lane = t & 31, wid = t >> 5;
    const unsigned* row = reinterpret_cast<const unsigned*>(g_cos + (size_t)n * kN);
#pragma unroll
    for (int i = 0; i < 4; i++) {
        unsigned x = row[t + 256 * i];
        x ^= (x & 0x80000000u) ? 0xFFFFFFFFu : 0x80000000u;  // order-preserving
        sv[t + 256 * i] = x;
    }
    if (t == 0) { s_need = kK; s_cntA = 0; s_cntT = 0; }
    unsigned prefix = 0;
    for (int shift = 24; shift >= 0; shift -= 8) {
        hist[t] = 0;
        __syncthreads();
        unsigned mask = (shift == 24) ? 0u : (0xFFFFFFFFu << (shift + 8));
#pragma unroll
        for (int i = 0; i < 4; i++) {
            unsigned x = sv[t + 256 * i];
            bool pred = (x & mask) == prefix;
            int d = (x >> shift) & 0xFF;
            int key = pred ? d : (0x100 + lane);
            unsigned peers = __match_any_sync(0xffffffffu, key);
            if (pred && (peers & ((1u << lane) - 1u)) == 0u)
                atomicAdd(&hist[d], __popc(peers));
        }
        __syncthreads();
        if (wid == 0) {  // suffix sums
            int base = 255 - 8 * lane;
            int loc[8], s = 0;
#pragma unroll
            for (int j = 0; j < 8; j++) { loc[j] = hist[base - j]; s += loc[j]; }
            int run = s;
#pragma unroll
            for (int off = 1; off < 32; off <<= 1) {
                int v = __shfl_up_sync(0xffffffffu, run, off);
                if (lane >= off) run += v;
            }
            int acc = run - s;
#pragma unroll
            for (int j = 0; j < 8; j++) { acc += loc[j]; suf[base - j] = acc; }
        }
        __syncthreads();
        int need = s_need;
        int above = (t == 255) ? 0 : suf[t + 1];
        if (suf[t] >= need && above < need) { s_digit = t; s_above = above; }
        __syncthreads();
        prefix |= ((unsigned)s_digit) << shift;
        if (t == 0) s_need -= s_above;
        __syncthreads();
    }
    unsigned T = prefix;
#pragma unroll
    for (int i = 0; i < 4; i++) {
        int m = t + 256 * i;
        unsigned x = sv[m];
        if (x > T)      { int p = atomicAdd(&s_cntA, 1); g_idx[n * kK + p] = m; }
        else if (x == T){ int p = atomicAdd(&s_cntT, 1); tie[p] = m; }
    }
    __syncthreads();
    int needT = kK - s_cntA;
    if (s_cntT == needT) {
        if (t < needT) g_idx[n * kK + s_cntA + t] = tie[t];
    } else {
        for (int r = 0; r < needT; r++) {
            int best = 0x7fffffff;
            for (int i = t; i < s_cntT; i += 256) best = min(best, tie[i]);
#pragma unroll
            for (int o = 16; o; o >>= 1) best = min(best, __shfl_xor_sync(0xffffffffu, best, o));
            if (lane == 0) wmin[wid] = best;
            __syncthreads();
            if (t == 0) {
                int m = 0x7fffffff;
                for (int w = 0; w < 8; w++) m = min(m, wmin[w]);
                g_idx[n * kK + s_cntA + r] = m;
                s_sel = m;
            }
            __syncthreads();
            for (int i = t; i < s_cntT; i += 256) if (tie[i] == s_sel) tie[i] = 0x7fffffff;
            __syncthreads();
        }
    }
}

// ---------------- kernel 3b: elementwise unnormalized weights ---------------
// e = exp(leaky(si+sj)) via tables: si+sj>0 <=> e^{si}e^{sj}>1. No reductions.
__global__ void k_alpha() {
    int lane = threadIdx.x & 31;
    int gw = (blockIdx.x * blockDim.x + threadIdx.x) >> 5;  // 16384 warps
#pragma unroll
    for (int j = 0; j < 4; j++) {
        int r = gw * 4 + j;
        int n = r & (kN - 1), bbase = r & ~(kN - 1);
        float2 ei = g_esi2[r];                  // lane-uniform broadcast
        if (lane < kK) {
            int id = g_idx[n * kK + lane];
            float2 ej = g_esj2[bbase + id];
            float f = ei.x * ej.x;
            float e = (f > 1.f) ? f : ei.y * ej.y;
            g_alpha[(size_t)r * kK + lane] = make_float2(e, __int_as_float(id));
        }
    }
}

// ---------------- BN affine finalize (inlined) ------------------------------
__device__ __forceinline__ void bn_ab(int d, const float* gm, const float* bt,
                                      const double* S, const double* Q,
                                      float& a, float& b) {
    double m = S[d] / (double)kM;
    double var = Q[d] / (double)kM - m * m;
    float inv = (float)(1.0 / sqrt(var + (double)kEps));
    a = gm[d] * inv;
    b = bt[d] - (float)m * a;
}

// ---------------- grid barrier (safe: grid=128, 1 block/SM, all resident) ---
__device__ __forceinline__ void grid_barrier(int which, int target) {
    __syncthreads();
    if (threadIdx.x == 0) {
        __threadfence();
        atomicAdd(&g_bar[which], 1);
        while (*(volatile int*)&g_bar[which] < target) __nanosleep(64);
    }
    __syncthreads();
}

// ---------------- kernel 4: fused gather + BN1 + BN2 stats + projection -----
// Block of 1024 threads per (b, half). h-half tile staged in 128 KB dyn smem;
// gather runs on the smem crossbar. Then grid barrier -> BN2 stats over own
// slice -> grid barrier -> (half==0 blocks) final projection.
__global__ void __launch_bounds__(1024, 1)
k_main(const float* __restrict__ gnn_bias, const float* __restrict__ emb,
       const float* __restrict__ g1, const float* __restrict__ b1v,
       const float* __restrict__ g2, const float* __restrict__ b2v,
       const float* __restrict__ out_w, const float* __restrict__ out_b,
       float* __restrict__ out) {
    extern __shared__ float sh[];              // [1024][32] = 128 KB
    __shared__ float4 sp4[32][40];             // 20 KB: per-warp 4 rows x 20 pairs
    __shared__ float  rs[32][32], rq[32][32];  // 8 KB
    __shared__ float  aff[4][kD];              // a1,b1,a2,b2
    __shared__ float  ws[kD];
    int t = threadIdx.x, lane = t & 31, wid = t >> 5;
    int sub = lane >> 3, li = lane & 7;
    int b = blockIdx.x >> 1, half = blockIdx.x & 1;
    const float* hb = g_h + (size_t)b * kN * kD + half * 32;
    // ---- stage h-half tile (coalesced: 32 lanes = one 128B row-half) ----
    for (int i = t; i < kN * 32; i += 1024)
        sh[i] = hb[(size_t)(i >> 5) * kD + (i & 31)];
    __syncthreads();
    const float4* sh4 = reinterpret_cast<const float4*>(sh);
    const float4* ga4 = reinterpret_cast<const float4*>(g_alpha);
    float4 bias4 = reinterpret_cast<const float4*>(gnn_bias)[half * 8 + li];
    float4 ts4 = make_float4(0.f, 0.f, 0.f, 0.f);
    float4 tq4 = make_float4(0.f, 0.f, 0.f, 0.f);
#pragma unroll 1
    for (int g = 0; g < 8; g++) {
        int n0 = (g * 32 + wid) * 4;
        size_t rowbase = (size_t)b * kN + n0;
        size_t gbase = rowbase * 10;
        sp4[wid][lane] = ga4[gbase + lane];
        if (lane < 8) sp4[wid][32 + lane] = ga4[gbase + 32 + lane];
        __syncwarp();
        float4 acc = make_float4(0.f, 0.f, 0.f, 0.f);
        float dn = 0.f;
#pragma unroll
        for (int k2 = 0; k2 < kK / 2; k2++) {
            float4 p = sp4[wid][sub * 10 + k2];   // (e0,id0,e1,id1)
            float4 v0 = sh4[__float_as_int(p.y) * 8 + li];
            float4 v1 = sh4[__float_as_int(p.w) * 8 + li];
            dn += p.x + p.z;
            acc.x = fmaf(p.x, v0.x, fmaf(p.z, v1.x, acc.x));
            acc.y = fmaf(p.x, v0.y, fmaf(p.z, v1.y, acc.y));
            acc.z = fmaf(p.x, v0.z, fmaf(p.z, v1.z, acc.z));
            acc.w = fmaf(p.x, v0.w, fmaf(p.z, v1.w, acc.w));
        }
        float inv = 1.0f / dn;
        float4 o4;
        o4.x = fmaf(acc.x, inv, bias4.x); o4.y = fmaf(acc.y, inv, bias4.y);
        o4.z = fmaf(acc.z, inv, bias4.z); o4.w = fmaf(acc.w, inv, bias4.w);
        reinterpret_cast<float4*>(
            g_out1 + (rowbase + sub) * kD + half * 32)[li] = o4;
        ts4.x += o4.x; ts4.y += o4.y; ts4.z += o4.z; ts4.w += o4.w;
        tq4.x = fmaf(o4.x, o4.x, tq4.x); tq4.y = fmaf(o4.y, o4.y, tq4.y);
        tq4.z = fmaf(o4.z, o4.z, tq4.z); tq4.w = fmaf(o4.w, o4.w, tq4.w);
        __syncwarp();
    }
#pragma unroll
    for (int off = 8; off <= 16; off <<= 1) {
        ts4.x += __shfl_xor_sync(0xffffffffu, ts4.x, off);
        ts4.y += __shfl_xor_sync(0xffffffffu, ts4.y, off);
        ts4.z += __shfl_xor_sync(0xffffffffu, ts4.z, off);
        ts4.w += __shfl_xor_sync(0xffffffffu, ts4.w, off);
        tq4.x += __shfl_xor_sync(0xffffffffu, tq4.x, off);
        tq4.y += __shfl_xor_sync(0xffffffffu, tq4.y, off);
        tq4.z += __shfl_xor_sync(0xffffffffu, tq4.z, off);
        tq4.w += __shfl_xor_sync(0xffffffffu, tq4.w, off);
    }
    if (sub == 0) {
        reinterpret_cast<float4*>(&rs[wid][0])[li] = ts4;
        reinterpret_cast<float4*>(&rq[wid][0])[li] = tq4;
    }
    __syncthreads();
    if (t < 32) {
        float s = 0.f, q = 0.f;
#pragma unroll 8
        for (int w = 0; w < 32; w++) { s += rs[w][t]; q += rq[w][t]; }
        atomicAdd(&g_sum1[half * 32 + t], (double)s);
        atomicAdd(&g_ssq1[half * 32 + t], (double)q);
    }
    // ================= phase B: BN2 stats over own slice =================
    grid_barrier(0, 2 * kB);
    if (t < 32) {
        float a, bb;
        bn_ab(half * 32 + t, g1, b1v, g_sum1, g_ssq1, a, bb);
        aff[0][t] = a; aff[1][t] = bb;
    }
    __syncthreads();
    {
        int c = t & 31, rg = t >> 5;
        float a1 = aff[0][c], b1 = aff[1][c];
        float ts = 0.f, tq = 0.f;
        for (int i = 0; i < 32; i++) {
            int row = rg * 32 + i;
            float x = g_out1[((size_t)b * kN + row) * kD + half * 32 + c];
            float y = fmaxf(fmaf(a1, x, b1), 0.f);
            float rep = y * emb[(size_t)row * kD + half * 32 + c];
            ts += rep; tq += rep * rep;
        }
        rs[rg][c] = ts; rq[rg][c] = tq;
    }
    __syncthreads();
    if (t < 32) {
        float s = 0.f, q = 0.f;
#pragma unroll 8
        for (int w = 0; w < 32; w++) { s += rs[w][t]; q += rq[w][t]; }
        atomicAdd(&g_sum2[half * 32 + t], (double)s);
        atomicAdd(&g_ssq2[half * 32 + t], (double)q);
    }
    // ================= phase C: final projection (half==0 blocks) =========
    grid_barrier(1, 2 * kB);
    if (half != 0) return;
    if (t < kD) {
        float a, bb;
        bn_ab(t, g1, b1v, g_sum1, g_ssq1, a, bb);
        aff[0][t] = a; aff[1][t] = bb;
        bn_ab(t, g2, b2v, g_sum2, g_ssq2, a, bb);
        aff[2][t] = a; aff[3][t] = bb;
        ws[t] = out_w[t];
    }
    __syncthreads();
    float ob = out_b[0];
    float a10 = aff[0][lane], b10 = aff[1][lane];
    float a11 = aff[0][lane + 32], b11 = aff[1][lane + 32];
    float a20 = aff[2][lane], b20 = aff[3][lane];
    float a21 = aff[2][lane + 32], b21 = aff[3][lane + 32];
    float w0 = ws[lane], w1 = ws[lane + 32];
    for (int n = wid; n < kN; n += 32) {
        size_t off = ((size_t)b * kN + n) * kD;
        float x0 = __ldcg(&g_out1[off + lane]);
        float x1 = __ldcg(&g_out1[off + lane + 32]);
        float y0 = fmaxf(fmaf(a10, x0, b10), 0.f) * emb[(size_t)n * kD + lane];
        float y1 = fmaxf(fmaf(a11, x1, b11), 0.f) * emb[(size_t)n * kD + lane + 32];
        float z0 = fmaxf(fmaf(a20, y0, b20), 0.f);
        float z1 = fmaxf(fmaf(a21, y1, b21), 0.f);
        float sred = z0 * w0 + z1 * w1;
#pragma unroll
        for (int o = 16; o; o >>= 1) sred += __shfl_xor_sync(0xffffffffu, sred, o);
        if (lane == 0) out[b * kN + n] = sred + ob;
    }
}

// ---------------- launch ----------------------------------------------------
extern "C" void kernel_launch(void* const* d_in, const int* in_sizes, int n_in,
                              void* d_out, int out_size) {
    const float* data     = (const float*)d_in[0];
    // d_in[1] = org_edge_index (int64) — unused by the reference
    const float* emb      = (const float*)d_in[2];
    const float* lin_w    = (const float*)d_in[3];
    const float* att_i    = (const float*)d_in[4];
    const float* att_j    = (const float*)d_in[5];
    const float* aei      = (const float*)d_in[6];
    const float* aej      = (const float*)d_in[7];
    const float* gnn_bias = (const float*)d_in[8];
    const float* g1       = (const float*)d_in[9];
    const float* b1       = (const float*)d_in[10];
    const float* g2       = (const float*)d_in[11];
    const float* b2       = (const float*)d_in[12];
    const float* out_w    = (const float*)d_in[13];
    const float* out_b    = (const float*)d_in[14];
    float* out = (float*)d_out;

    static int attr_set = 0;
    if (!attr_set) {
        cudaFuncSetAttribute(k_main, cudaFuncAttributeMaxDynamicSharedMemorySize,
                             kN * 32 * (int)sizeof(float));
        attr_set = 1;
    }

    k_cos<<<dim3(16, 16), 256>>>(emb, aei, aej);
    k_h<<<2048, 256>>>(data, lin_w, att_i, att_j);
    k_topk<<<1024, 256>>>();
    k_alpha<<<2048, 256>>>();
    k_main<<<128, 1024, kN * 32 * sizeof(float)>>>(gnn_bias, emb, g1, b1, g2, b2,
                                                   out_w, out_b, out);
}

// round 12
// speedup vs baseline: 1.2311x; 1.2311x over previous
#include <cuda_runtime.h>
#include <math.h>

// Problem constants
constexpr int kB = 64, kN = 1024, kF = 16, kD = 64, kK = 20;
constexpr int kM = kB * kN;              // 65536 rows
constexpr float kEps = 1e-5f, kSlope = 0.2f;

// ---------------- scratch (device globals: allocation-free) ----------------
__device__ float  g_h[(size_t)kM * kD];      // 16 MB
__device__ float  g_out1[(size_t)kM * kD];   // 16 MB
__device__ float2 g_esi2[kM];                // {e^si, e^{0.2 si}}
__device__ float2 g_esj2[kM];                // {e^sj, e^{0.2 sj}}
__device__ float  g_emi[kN];
__device__ float  g_emj[kN];
__device__ float  g_cos[(size_t)kN * kN];    // 4 MB
__device__ int    g_idx[kN * kK];
__device__ double g_sum1[kD], g_ssq1[kD], g_sum2[kD], g_ssq2[kD];

// ---------------- kernel 1: cosine Gram + norms + emb-att dots + zeroing ----
__global__ void k_cos(const float* __restrict__ emb,
                      const float* __restrict__ aei,
                      const float* __restrict__ aej) {
    __shared__ float As[kD][65];
    __shared__ float Bs[kD][65];
    __shared__ float rnA[64], rnB[64];
    int t = threadIdx.x;
    int bn = blockIdx.y * 64, bm = blockIdx.x * 64;
    if (blockIdx.x == 0 && blockIdx.y == 0 && t < kD) {
        g_sum1[t] = 0.0; g_ssq1[t] = 0.0; g_sum2[t] = 0.0; g_ssq2[t] = 0.0;
    }
    for (int idx = t; idx < 64 * 64; idx += 256) {
        int r = idx >> 6, k = idx & 63;
        As[k][r] = emb[(size_t)(bn + r) * kD + k];
        Bs[k][r] = emb[(size_t)(bm + r) * kD + k];
    }
    __syncthreads();
    if (t < 64) {
        float s = 0.f;
        for (int k = 0; k < 64; k++) { float v = As[k][t]; s += v * v; }
        rnA[t] = 1.0f / sqrtf(s);
    } else if (t < 128) {
        int r = t - 64;
        float s = 0.f;
        for (int k = 0; k < 64; k++) { float v = Bs[k][r]; s += v * v; }
        rnB[r] = 1.0f / sqrtf(s);
    } else if (blockIdx.x == 0) {
        int r = (t - 128) & 63;
        const float* av = (t < 192) ? aei : aej;
        float s = 0.f;
        for (int k = 0; k < 64; k++) s += As[k][r] * av[k];
        if (t < 192) g_emi[bn + r] = s; else g_emj[bn + r] = s;
    }
    int tx = t & 15, ty = t >> 4;
    float acc[4][4] = {};
#pragma unroll 4
    for (int k = 0; k < 64; k++) {
        float a[4], b[4];
#pragma unroll
        for (int i = 0; i < 4; i++) { a[i] = As[k][ty * 4 + i]; b[i] = Bs[k][tx * 4 + i]; }
#pragma unroll
        for (int i = 0; i < 4; i++)
#pragma unroll
            for (int j = 0; j < 4; j++) acc[i][j] += a[i] * b[j];
    }
    __syncthreads();
#pragma unroll
    for (int i = 0; i < 4; i++) {
        int r = bn + ty * 4 + i;
        float rn = rnA[ty * 4 + i];
#pragma unroll
        for (int j = 0; j < 4; j++) {
            int c = bm + tx * 4 + j;
            g_cos[(size_t)r * kN + c] = acc[i][j] * rn * rnB[tx * 4 + j];
        }
    }
}

// ---------------- kernel 2: h = data @ lin_w^T + exp tables -----------------
__global__ void k_h(const float* __restrict__ data, const float* __restrict__ lin_w,
                    const float* __restrict__ att_i, const float* __restrict__ att_j) {
    __shared__ float lw[kF][kD];
    for (int idx = threadIdx.x; idx < kF * kD; idx += blockDim.x) {
        int f = idx >> 6, d = idx & 63;
        lw[f][d] = lin_w[d * kF + f];
    }
    __syncthreads();
    int lane = threadIdx.x & 31;
    int gw = (blockIdx.x * blockDim.x + threadIdx.x) >> 5;
    int nw = (gridDim.x * blockDim.x) >> 5;
    float ai0 = att_i[lane], ai1 = att_i[lane + 32];
    float aj0 = att_j[lane], aj1 = att_j[lane + 32];
    for (int r = gw; r < kM; r += nw) {
        const float4* dp = reinterpret_cast<const float4*>(data + (size_t)r * kF);
        float4 q0 = dp[0], q1 = dp[1], q2 = dp[2], q3 = dp[3];
        float df[16] = {q0.x, q0.y, q0.z, q0.w, q1.x, q1.y, q1.z, q1.w,
                        q2.x, q2.y, q2.z, q2.w, q3.x, q3.y, q3.z, q3.w};
        float h0 = 0.f, h1 = 0.f;
#pragma unroll
        for (int f = 0; f < 16; f++) {
            h0 += df[f] * lw[f][lane];
            h1 += df[f] * lw[f][lane + 32];
        }
        g_h[(size_t)r * kD + lane] = h0;
        g_h[(size_t)r * kD + lane + 32] = h1;
        float si = h0 * ai0 + h1 * ai1;
        float sj = h0 * aj0 + h1 * aj1;
#pragma unroll
        for (int o = 16; o; o >>= 1) {
            si += __shfl_xor_sync(0xffffffffu, si, o);
            sj += __shfl_xor_sync(0xffffffffu, sj, o);
        }
        if (lane == 0) {
            int n = r & (kN - 1);
            float siv = si + g_emi[n], sjv = sj + g_emj[n];
            g_esi2[r] = make_float2(expf(siv), expf(0.2f * siv));
            g_esj2[r] = make_float2(expf(sjv), expf(0.2f * sjv));
        }
    }
}

// ---------------- kernel 3: exact top-20 via 4-pass 8-bit radix select ------
__global__ void k_topk() {
    __shared__ unsigned sv[kN];
    __shared__ int hist[256];
    __shared__ int suf[256];
    __shared__ int tie[kN];
    __shared__ int s_digit, s_above, s_need, s_cntA, s_cntT, s_sel;
    __shared__ int wmin[8];
    int n = blockIdx.x, t = threadIdx.x;
    int lane = t & 31, wid = t >> 5;
    const unsigned* row = reinterpret_cast<const unsigned*>(g_cos + (size_t)n * kN);
#pragma unroll
    for (int i = 0; i < 4; i++) {
        unsigned x = row[t + 256 * i];
        x ^= (x & 0x80000000u) ? 0xFFFFFFFFu : 0x80000000u;  // order-preserving
        sv[t + 256 * i] = x;
    }
    if (t == 0) { s_need = kK; s_cntA = 0; s_cntT = 0; }
    unsigned prefix = 0;
    for (int shift = 24; shift >= 0; shift -= 8) {
        hist[t] = 0;
        __syncthreads();
        unsigned mask = (shift == 24) ? 0u : (0xFFFFFFFFu << (shift + 8));
#pragma unroll
        for (int i = 0; i < 4; i++) {
            unsigned x = sv[t + 256 * i];
            bool pred = (x & mask) == prefix;
            int d = (x >> shift) & 0xFF;
            int key = pred ? d : (0x100 + lane);
            unsigned peers = __match_any_sync(0xffffffffu, key);
            if (pred && (peers & ((1u << lane) - 1u)) == 0u)
                atomicAdd(&hist[d], __popc(peers));
        }
        __syncthreads();
        if (wid == 0) {  // suffix sums
            int base = 255 - 8 * lane;
            int loc[8], s = 0;
#pragma unroll
            for (int j = 0; j < 8; j++) { loc[j] = hist[base - j]; s += loc[j]; }
            int run = s;
#pragma unroll
            for (int off = 1; off < 32; off <<= 1) {
                int v = __shfl_up_sync(0xffffffffu, run, off);
                if (lane >= off) run += v;
            }
            int acc = run - s;
#pragma unroll
            for (int j = 0; j < 8; j++) { acc += loc[j]; suf[base - j] = acc; }
        }
        __syncthreads();
        int need = s_need;
        int above = (t == 255) ? 0 : suf[t + 1];
        if (suf[t] >= need && above < need) { s_digit = t; s_above = above; }
        __syncthreads();
        prefix |= ((unsigned)s_digit) << shift;
        if (t == 0) s_need -= s_above;
        __syncthreads();
    }
    unsigned T = prefix;
#pragma unroll
    for (int i = 0; i < 4; i++) {
        int m = t + 256 * i;
        unsigned x = sv[m];
        if (x > T)      { int p = atomicAdd(&s_cntA, 1); g_idx[n * kK + p] = m; }
        else if (x == T){ int p = atomicAdd(&s_cntT, 1); tie[p] = m; }
    }
    __syncthreads();
    int needT = kK - s_cntA;
    if (s_cntT == needT) {
        if (t < needT) g_idx[n * kK + s_cntA + t] = tie[t];
    } else {
        for (int r = 0; r < needT; r++) {
            int best = 0x7fffffff;
            for (int i = t; i < s_cntT; i += 256) best = min(best, tie[i]);
#pragma unroll
            for (int o = 16; o; o >>= 1) best = min(best, __shfl_xor_sync(0xffffffffu, best, o));
            if (lane == 0) wmin[wid] = best;
            __syncthreads();
            if (t == 0) {
                int m = 0x7fffffff;
                for (int w = 0; w < 8; w++) m = min(m, wmin[w]);
                g_idx[n * kK + s_cntA + r] = m;
                s_sel = m;
            }
            __syncthreads();
            for (int i = t; i < s_cntT; i += 256) if (tie[i] == s_sel) tie[i] = 0x7fffffff;
            __syncthreads();
        }
    }
}

// ---------------- kernel 4: inline alpha + smem gather + BN1 stats ----------
// Block of 1024 threads per (b, half). h-half tile (128 KB) + esi2/esj2 tables
// (16 KB) staged in smem. Unnormalized weights computed inline from the exp
// tables (e = exp(leaky(si+sj)); si+sj>0 <=> e^si*e^sj>1); gather runs on the
// smem crossbar via LDS.128; per-row denominator summed in-register.
__global__ void __launch_bounds__(1024, 1)
k_main(const float* __restrict__ gnn_bias) {
    extern __shared__ float sh[];              // [1024][32] = 128 KB
    __shared__ float4 sp4[32][40];             // 20 KB
    __shared__ float  rs[32][32], rq[32][32];  // 8 KB
    __shared__ float2 ssi[kN], ssj[kN];        // 16 KB
    int t = threadIdx.x, lane = t & 31, wid = t >> 5;
    int sub = lane >> 3, li = lane & 7;
    int b = blockIdx.x >> 1, half = blockIdx.x & 1;
    const float* hb = g_h + (size_t)b * kN * kD + half * 32;
    for (int i = t; i < kN * 32; i += 1024)
        sh[i] = hb[(size_t)(i >> 5) * kD + (i & 31)];
    for (int i = t; i < kN; i += 1024) {
        ssi[i] = g_esi2[b * kN + i];
        ssj[i] = g_esj2[b * kN + i];
    }
    __syncthreads();
    const float4* sh4 = reinterpret_cast<const float4*>(sh);
    const int2* idx2 = reinterpret_cast<const int2*>(g_idx);   // 10 int2 per row
    float4 bias4 = reinterpret_cast<const float4*>(gnn_bias)[half * 8 + li];
    float4 ts4 = make_float4(0.f, 0.f, 0.f, 0.f);
    float4 tq4 = make_float4(0.f, 0.f, 0.f, 0.f);
#pragma unroll 1
    for (int g = 0; g < 8; g++) {
        int n0 = (g * 32 + wid) * 4;
        // fill sp4[wid][0..39]: entry idx -> row r=idx/10, pair j=idx%10
#pragma unroll
        for (int pass = 0; pass < 2; pass++) {
            int idx = lane + pass * 32;
            if (idx < 40) {
                int r = idx / 10, j = idx - r * 10;
                int n = n0 + r;
                int2 ids = idx2[n * 10 + j];
                float2 ei = ssi[n];
                float2 e0 = ssj[ids.x], e1 = ssj[ids.y];
                float f0 = ei.x * e0.x, f1 = ei.x * e1.x;
                float w0 = (f0 > 1.f) ? f0 : ei.y * e0.y;
                float w1 = (f1 > 1.f) ? f1 : ei.y * e1.y;
                sp4[wid][idx] = make_float4(w0, __int_as_float(ids.x),
                                            w1, __int_as_float(ids.y));
            }
        }
        __syncwarp();
        float4 acc = make_float4(0.f, 0.f, 0.f, 0.f);
        float dn = 0.f;
#pragma unroll
        for (int k2 = 0; k2 < kK / 2; k2++) {
            float4 p = sp4[wid][sub * 10 + k2];   // (e0,id0,e1,id1)
            float4 v0 = sh4[__float_as_int(p.y) * 8 + li];
            float4 v1 = sh4[__float_as_int(p.w) * 8 + li];
            dn += p.x + p.z;
            acc.x = fmaf(p.x, v0.x, fmaf(p.z, v1.x, acc.x));
            acc.y = fmaf(p.x, v0.y, fmaf(p.z, v1.y, acc.y));
            acc.z = fmaf(p.x, v0.z, fmaf(p.z, v1.z, acc.z));
            acc.w = fmaf(p.x, v0.w, fmaf(p.z, v1.w, acc.w));
        }
        float inv = 1.0f / dn;
        float4 o4;
        o4.x = fmaf(acc.x, inv, bias4.x); o4.y = fmaf(acc.y, inv, bias4.y);
        o4.z = fmaf(acc.z, inv, bias4.z); o4.w = fmaf(acc.w, inv, bias4.w);
        reinterpret_cast<float4*>(
            g_out1 + ((size_t)b * kN + n0 + sub) * kD + half * 32)[li] = o4;
        ts4.x += o4.x; ts4.y += o4.y; ts4.z += o4.z; ts4.w += o4.w;
        tq4.x = fmaf(o4.x, o4.x, tq4.x); tq4.y = fmaf(o4.y, o4.y, tq4.y);
        tq4.z = fmaf(o4.z, o4.z, tq4.z); tq4.w = fmaf(o4.w, o4.w, tq4.w);
        __syncwarp();                          // WAR on sp4[wid]
    }
#pragma unroll
    for (int off = 8; off <= 16; off <<= 1) {
        ts4.x += __shfl_xor_sync(0xffffffffu, ts4.x, off);
        ts4.y += __shfl_xor_sync(0xffffffffu, ts4.y, off);
        ts4.z += __shfl_xor_sync(0xffffffffu, ts4.z, off);
        ts4.w += __shfl_xor_sync(0xffffffffu, ts4.w, off);
        tq4.x += __shfl_xor_sync(0xffffffffu, tq4.x, off);
        tq4.y += __shfl_xor_sync(0xffffffffu, tq4.y, off);
        tq4.z += __shfl_xor_sync(0xffffffffu, tq4.z, off);
        tq4.w += __shfl_xor_sync(0xffffffffu, tq4.w, off);
    }
    if (sub == 0) {
        reinterpret_cast<float4*>(&rs[wid][0])[li] = ts4;
        reinterpret_cast<float4*>(&rq[wid][0])[li] = tq4;
    }
    __syncthreads();
    if (t < 32) {
        float s = 0.f, q = 0.f;
#pragma unroll 8
        for (int w = 0; w < 32; w++) { s += rs[w][t]; q += rq[w][t]; }
        atomicAdd(&g_sum1[half * 32 + t], (double)s);
        atomicAdd(&g_ssq1[half * 32 + t], (double)q);
    }
}

// ---------------- BN affine finalize (inlined) ------------------------------
__device__ __forceinline__ void bn_ab(int d, const float* gm, const float* bt,
                                      const double* S, const double* Q,
                                      float& a, float& b) {
    double m = S[d] / (double)kM;
    double var = Q[d] / (double)kM - m * m;
    float inv = (float)(1.0 / sqrt(var + (double)kEps));
    a = gm[d] * inv;
    b = bt[d] - (float)m * a;
}

// ---------------- kernel 5: BN2 statistics ----------------------------------
__global__ void k_stats2(const float* __restrict__ emb,
                         const float* __restrict__ g1, const float* __restrict__ b1v) {
    int t = threadIdx.x;
    int c = t & 63, rg = t >> 6;
    float a1, b1; bn_ab(c, g1, b1v, g_sum1, g_ssq1, a1, b1);
    float ts = 0.f, tq = 0.f;
    int r0 = blockIdx.x * 64;
    for (int i = 0; i < 16; i++) {
        int r = r0 + rg * 16 + i;
        float x = g_out1[(size_t)r * kD + c];
        float y = fmaxf(fmaf(a1, x, b1), 0.f);
        float rep = y * emb[(size_t)(r & (kN - 1)) * kD + c];
        ts += rep; tq += rep * rep;
    }
    __shared__ float rs[4][kD], rq[4][kD];
    rs[rg][c] = ts; rq[rg][c] = tq;
    __syncthreads();
    if (t < kD) {
        float s = 0.f, q = 0.f;
        for (int g = 0; g < 4; g++) { s += rs[g][t]; q += rq[g][t]; }
        atomicAdd(&g_sum2[t], (double)s);
        atomicAdd(&g_ssq2[t], (double)q);
    }
}

// ---------------- kernel 6: final projection --------------------------------
__global__ void k_final(const float* __restrict__ emb, const float* __restrict__ out_w,
                        const float* __restrict__ out_b,
                        const float* __restrict__ g1, const float* __restrict__ b1v,
                        const float* __restrict__ g2, const float* __restrict__ b2v,
                        float* __restrict__ out) {
    int lane = threadIdx.x & 31;
    int gw = (blockIdx.x * blockDim.x + threadIdx.x) >> 5;
    int nw = (gridDim.x * blockDim.x) >> 5;
    float a10, b10, a11, b11, a20, b20, a21, b21;
    bn_ab(lane,      g1, b1v, g_sum1, g_ssq1, a10, b10);
    bn_ab(lane + 32, g1, b1v, g_sum1, g_ssq1, a11, b11);
    bn_ab(lane,      g2, b2v, g_sum2, g_ssq2, a20, b20);
    bn_ab(lane + 32, g2, b2v, g_sum2, g_ssq2, a21, b21);
    float w0 = out_w[lane], w1 = out_w[lane + 32];
    float ob = out_b[0];
    for (int r = gw; r < kM; r += nw) {
        int n = r & (kN - 1);
        float x0 = g_out1[(size_t)r * kD + lane];
        float x1 = g_out1[(size_t)r * kD + lane + 32];
        float y0 = fmaxf(fmaf(a10, x0, b10), 0.f) * emb[(size_t)n * kD + lane];
        float y1 = fmaxf(fmaf(a11, x1, b11), 0.f) * emb[(size_t)n * kD + lane + 32];
        float z0 = fmaxf(fmaf(a20, y0, b20), 0.f);
        float z1 = fmaxf(fmaf(a21, y1, b21), 0.f);
        float sred = z0 * w0 + z1 * w1;
#pragma unroll
        for (int o = 16; o; o >>= 1) sred += __shfl_xor_sync(0xffffffffu, sred, o);
        if (lane == 0) out[r] = sred + ob;
    }
}

// ---------------- launch ----------------------------------------------------
extern "C" void kernel_launch(void* const* d_in, const int* in_sizes, int n_in,
                              void* d_out, int out_size) {
    const float* data     = (const float*)d_in[0];
    // d_in[1] = org_edge_index (int64) — unused by the reference
    const float* emb      = (const float*)d_in[2];
    const float* lin_w    = (const float*)d_in[3];
    const float* att_i    = (const float*)d_in[4];
    const float* att_j    = (const float*)d_in[5];
    const float* aei      = (const float*)d_in[6];
    const float* aej      = (const float*)d_in[7];
    const float* gnn_bias = (const float*)d_in[8];
    const float* g1       = (const float*)d_in[9];
    const float* b1       = (const float*)d_in[10];
    const float* g2       = (const float*)d_in[11];
    const float* b2       = (const float*)d_in[12];
    const float* out_w    = (const float*)d_in[13];
    const float* out_b    = (const float*)d_in[14];
    float* out = (float*)d_out;

    cudaFuncSetAttribute(k_main, cudaFuncAttributeMaxDynamicSharedMemorySize,
                         kN * 32 * (int)sizeof(float));

    k_cos<<<dim3(16, 16), 256>>>(emb, aei, aej);
    k_h<<<2048, 256>>>(data, lin_w, att_i, att_j);
    k_topk<<<1024, 256>>>();
    k_main<<<128, 1024, kN * 32 * sizeof(float)>>>(gnn_bias);
    k_stats2<<<1024, 256>>>(emb, g1, b1);
    k_final<<<512, 256>>>(emb, out_w, out_b, g1, b1, g2, b2, out);
}

// round 13
// speedup vs baseline: 1.7916x; 1.4553x over previous
#include <cuda_runtime.h>
#include <math.h>

// Problem constants
constexpr int kB = 64, kN = 1024, kF = 16, kD = 64, kK = 20;
constexpr int kM = kB * kN;              // 65536 rows
constexpr float kEps = 1e-5f, kSlope = 0.2f;

// ---------------- scratch (device globals: allocation-free) ----------------
__device__ float  g_h[(size_t)kM * kD];      // 16 MB
__device__ float  g_out1[(size_t)kM * kD];   // 16 MB
__device__ float2 g_esi2[kM];                // {e^si, e^{0.2 si}}
__device__ float2 g_esj2[kM];                // {e^sj, e^{0.2 sj}}
__device__ float  g_emi[kN];
__device__ float  g_emj[kN];
__device__ float  g_cos[(size_t)kN * kN];    // 4 MB
__device__ int    g_idx[kN * kK];
__device__ double g_sum1[kD], g_ssq1[kD], g_sum2[kD], g_ssq2[kD];

// ---------------- kernel 1: cosine Gram + norms + emb-att dots + zeroing ----
__global__ void k_cos(const float* __restrict__ emb,
                      const float* __restrict__ aei,
                      const float* __restrict__ aej) {
    __shared__ float As[kD][68];   // row stride 272 B (16B-aligned): float4 reads
    __shared__ float Bs[kD][68];
    __shared__ float rnA[64], rnB[64];
    int t = threadIdx.x;
    int bn = blockIdx.y * 64, bm = blockIdx.x * 64;
    if (blockIdx.x == 0 && blockIdx.y == 0 && t < kD) {
        g_sum1[t] = 0.0; g_ssq1[t] = 0.0; g_sum2[t] = 0.0; g_ssq2[t] = 0.0;
    }
    for (int idx = t; idx < 64 * 64; idx += 256) {
        int r = idx >> 6, k = idx & 63;
        As[k][r] = emb[(size_t)(bn + r) * kD + k];
        Bs[k][r] = emb[(size_t)(bm + r) * kD + k];
    }
    __syncthreads();
    if (t < 64) {
        float s = 0.f;
        for (int k = 0; k < 64; k++) { float v = As[k][t]; s += v * v; }
        rnA[t] = 1.0f / sqrtf(s);
    } else if (t < 128) {
        int r = t - 64;
        float s = 0.f;
        for (int k = 0; k < 64; k++) { float v = Bs[k][r]; s += v * v; }
        rnB[r] = 1.0f / sqrtf(s);
    } else if (blockIdx.x == 0) {
        int r = (t - 128) & 63;
        const float* av = (t < 192) ? aei : aej;
        float s = 0.f;
        for (int k = 0; k < 64; k++) s += As[k][r] * av[k];
        if (t < 192) g_emi[bn + r] = s; else g_emj[bn + r] = s;
    }
    int tx = t & 15, ty = t >> 4;
    float acc[4][4] = {};
#pragma unroll 4
    for (int k = 0; k < 64; k++) {
        float4 a4 = *reinterpret_cast<const float4*>(&As[k][ty * 4]);
        float4 b4 = *reinterpret_cast<const float4*>(&Bs[k][tx * 4]);
        float a[4] = {a4.x, a4.y, a4.z, a4.w};
        float b[4] = {b4.x, b4.y, b4.z, b4.w};
#pragma unroll
        for (int i = 0; i < 4; i++)
#pragma unroll
            for (int j = 0; j < 4; j++) acc[i][j] += a[i] * b[j];
    }
    __syncthreads();
#pragma unroll
    for (int i = 0; i < 4; i++) {
        int r = bn + ty * 4 + i;
        float rn = rnA[ty * 4 + i];
#pragma unroll
        for (int j = 0; j < 4; j++) {
            int c = bm + tx * 4 + j;
            g_cos[(size_t)r * kN + c] = acc[i][j] * rn * rnB[tx * 4 + j];
        }
    }
}

// ---------------- kernel 2: h = data @ lin_w^T + exp tables -----------------
__global__ void k_h(const float* __restrict__ data, const float* __restrict__ lin_w,
                    const float* __restrict__ att_i, const float* __restrict__ att_j) {
    __shared__ float lw[kF][kD];
    for (int idx = threadIdx.x; idx < kF * kD; idx += blockDim.x) {
        int f = idx >> 6, d = idx & 63;
        lw[f][d] = lin_w[d * kF + f];
    }
    __syncthreads();
    int lane = threadIdx.x & 31;
    int gw = (blockIdx.x * blockDim.x + threadIdx.x) >> 5;
    int nw = (gridDim.x * blockDim.x) >> 5;
    float ai0 = att_i[lane], ai1 = att_i[lane + 32];
    float aj0 = att_j[lane], aj1 = att_j[lane + 32];
    for (int r = gw; r < kM; r += nw) {
        const float4* dp = reinterpret_cast<const float4*>(data + (size_t)r * kF);
        float4 q0 = dp[0], q1 = dp[1], q2 = dp[2], q3 = dp[3];
        float df[16] = {q0.x, q0.y, q0.z, q0.w, q1.x, q1.y, q1.z, q1.w,
                        q2.x, q2.y, q2.z, q2.w, q3.x, q3.y, q3.z, q3.w};
        float h0 = 0.f, h1 = 0.f;
#pragma unroll
        for (int f = 0; f < 16; f++) {
            h0 += df[f] * lw[f][lane];
            h1 += df[f] * lw[f][lane + 32];
        }
        g_h[(size_t)r * kD + lane] = h0;
        g_h[(size_t)r * kD + lane + 32] = h1;
        float si = h0 * ai0 + h1 * ai1;
        float sj = h0 * aj0 + h1 * aj1;
#pragma unroll
        for (int o = 16; o; o >>= 1) {
            si += __shfl_xor_sync(0xffffffffu, si, o);
            sj += __shfl_xor_sync(0xffffffffu, sj, o);
        }
        if (lane == 0) {
            int n = r & (kN - 1);
            float siv = si + g_emi[n], sjv = sj + g_emj[n];
            g_esi2[r] = make_float2(expf(siv), expf(0.2f * siv));
            g_esj2[r] = make_float2(expf(sjv), expf(0.2f * sjv));
        }
    }
}

// ---------------- kernel 3: top-20 radix select with candidate compaction ---
// Pass 1 histograms all 1024 (plain smem atomics: <=32cyc/warp even fully
// conflicted). Survivors (top byte == threshold digit) are compacted; passes
// 2-4 touch only the compacted list. Ties at the exact K-th value take the
// lowest indices (jax.lax.top_k set semantics).
__global__ void k_topk() {
    __shared__ unsigned sv[kN];
    __shared__ int hist[256];
    __shared__ int suf[257];
    __shared__ unsigned cva[kN]; __shared__ int cia[kN];
    __shared__ unsigned cvb[kN]; __shared__ int cib[kN];
    __shared__ int s_digit, s_need, s_out, s_ca, s_cb, s_sel;
    __shared__ int wmin[8];
    int n = blockIdx.x, t = threadIdx.x;
    int lane = t & 31, wid = t >> 5;
    const unsigned* row = reinterpret_cast<const unsigned*>(g_cos + (size_t)n * kN);
#pragma unroll
    for (int i = 0; i < 4; i++) {
        unsigned x = row[t + 256 * i];
        x ^= (x & 0x80000000u) ? 0xFFFFFFFFu : 0x80000000u;  // order-preserving
        sv[t + 256 * i] = x;
    }
    hist[t] = 0;
    if (t == 0) { s_need = kK; s_out = 0; s_ca = 0; suf[256] = 0; }
    __syncthreads();
    // ---- pass 1: top byte over all 1024 ----
#pragma unroll
    for (int i = 0; i < 4; i++)
        atomicAdd(&hist[sv[t + 256 * i] >> 24], 1);
    __syncthreads();
    if (wid == 0) {  // suffix sums: suf[e] = count of digit >= e
        int base = 255 - 8 * lane;
        int loc[8], s = 0;
#pragma unroll
        for (int j = 0; j < 8; j++) { loc[j] = hist[base - j]; s += loc[j]; }
        int run = s;
#pragma unroll
        for (int off = 1; off < 32; off <<= 1) {
            int v = __shfl_up_sync(0xffffffffu, run, off);
            if (lane >= off) run += v;
        }
        int acc = run - s;
#pragma unroll
        for (int j = 0; j < 8; j++) { acc += loc[j]; suf[base - j] = acc; }
    }
    __syncthreads();
    {
        int need = s_need;
        if (suf[t] >= need && suf[t + 1] < need) s_digit = t;
    }
    __syncthreads();
    {
        int digit = s_digit;
        int above = suf[digit + 1];
#pragma unroll
        for (int i = 0; i < 4; i++) {
            int m = t + 256 * i;
            unsigned x = sv[m];
            int d = x >> 24;
            if (d > digit)       { int p = atomicAdd(&s_out, 1); g_idx[n * kK + p] = m; }
            else if (d == digit) { int p = atomicAdd(&s_ca, 1); cva[p] = x; cia[p] = m; }
        }
        if (t == 0) s_need = kK - above;
    }
    __syncthreads();
    // ---- passes 2-4 over compacted candidates ----
    unsigned* cv = cva; int* ci = cia;
    unsigned* nv = cvb; int* niv = cib;
    int C = s_ca;
    for (int shift = 16; shift >= 0; shift -= 8) {
        hist[t] = 0;
        if (t == 0) s_cb = 0;
        __syncthreads();
        for (int i = t; i < C; i += 256)
            atomicAdd(&hist[(cv[i] >> shift) & 255], 1);
        __syncthreads();
        if (wid == 0) {
            int base = 255 - 8 * lane;
            int loc[8], s = 0;
#pragma unroll
            for (int j = 0; j < 8; j++) { loc[j] = hist[base - j]; s += loc[j]; }
            int run = s;
#pragma unroll
            for (int off = 1; off < 32; off <<= 1) {
                int v = __shfl_up_sync(0xffffffffu, run, off);
                if (lane >= off) run += v;
            }
            int acc = run - s;
#pragma unroll
            for (int j = 0; j < 8; j++) { acc += loc[j]; suf[base - j] = acc; }
        }
        __syncthreads();
        int need = s_need;
        if (suf[t] >= need && suf[t + 1] < need) s_digit = t;
        __syncthreads();
        int digit = s_digit;
        int above = suf[digit + 1];
        for (int i = t; i < C; i += 256) {
            unsigned x = cv[i];
            int d = (x >> shift) & 255;
            if (d > digit)       { int p = atomicAdd(&s_out, 1); g_idx[n * kK + p] = ci[i]; }
            else if (d == digit) { int p = atomicAdd(&s_cb, 1); nv[p] = x; niv[p] = ci[i]; }
        }
        if (t == 0) s_need = need - above;
        __syncthreads();
        C = s_cb;
        unsigned* tv = cv; cv = nv; nv = tv;
        int* ti = ci; ci = niv; niv = ti;
    }
    // ---- remaining R entries all equal the exact K-th value ----
    int R = s_need;
    int base = kK - R;
    if (C == R) {
        if (t < R) g_idx[n * kK + base + t] = ci[t];
    } else {  // rare: multiplicity at threshold -> lowest indices win
        for (int r = 0; r < R; r++) {
            int best = 0x7fffffff;
            for (int i = t; i < C; i += 256) best = min(best, ci[i]);
#pragma unroll
            for (int o = 16; o; o >>= 1) best = min(best, __shfl_xor_sync(0xffffffffu, best, o));
            if (lane == 0) wmin[wid] = best;
            __syncthreads();
            if (t == 0) {
                int m = 0x7fffffff;
                for (int w = 0; w < 8; w++) m = min(m, wmin[w]);
                g_idx[n * kK + base + r] = m;
                s_sel = m;
            }
            __syncthreads();
            for (int i = t; i < C; i += 256) if (ci[i] == s_sel) ci[i] = 0x7fffffff;
            __syncthreads();
        }
    }
}

// ---------------- kernel 4: inline alpha + smem gather + BN1 stats ----------
__global__ void __launch_bounds__(1024, 1)
k_main(const float* __restrict__ gnn_bias) {
    extern __shared__ float sh[];              // [1024][32] = 128 KB
    __shared__ float4 sp4[32][40];             // 20 KB
    __shared__ float  rs[32][32], rq[32][32];  // 8 KB
    __shared__ float2 ssi[kN], ssj[kN];        // 16 KB
    int t = threadIdx.x, lane = t & 31, wid = t >> 5;
    int sub = lane >> 3, li = lane & 7;
    int b = blockIdx.x >> 1, half = blockIdx.x & 1;
    const float* hb = g_h + (size_t)b * kN * kD + half * 32;
    for (int i = t; i < kN * 32; i += 1024)
        sh[i] = hb[(size_t)(i >> 5) * kD + (i & 31)];
    for (int i = t; i < kN; i += 1024) {
        ssi[i] = g_esi2[b * kN + i];
        ssj[i] = g_esj2[b * kN + i];
    }
    __syncthreads();
    const float4* sh4 = reinterpret_cast<const float4*>(sh);
    const int2* idx2 = reinterpret_cast<const int2*>(g_idx);   // 10 int2 per row
    float4 bias4 = reinterpret_cast<const float4*>(gnn_bias)[half * 8 + li];
    float4 ts4 = make_float4(0.f, 0.f, 0.f, 0.f);
    float4 tq4 = make_float4(0.f, 0.f, 0.f, 0.f);
#pragma unroll 1
    for (int g = 0; g < 8; g++) {
        int n0 = (g * 32 + wid) * 4;
#pragma unroll
        for (int pass = 0; pass < 2; pass++) {
            int idx = lane + pass * 32;
            if (idx < 40) {
                int r = idx / 10, j = idx - r * 10;
                int n = n0 + r;
                int2 ids = idx2[n * 10 + j];
                float2 ei = ssi[n];
                float2 e0 = ssj[ids.x], e1 = ssj[ids.y];
                float f0 = ei.x * e0.x, f1 = ei.x * e1.x;
                float w0 = (f0 > 1.f) ? f0 : ei.y * e0.y;
                float w1 = (f1 > 1.f) ? f1 : ei.y * e1.y;
                sp4[wid][idx] = make_float4(w0, __int_as_float(ids.x),
                                            w1, __int_as_float(ids.y));
            }
        }
        __syncwarp();
        float4 acc = make_float4(0.f, 0.f, 0.f, 0.f);
        float dn = 0.f;
#pragma unroll
        for (int k2 = 0; k2 < kK / 2; k2++) {
            float4 p = sp4[wid][sub * 10 + k2];   // (e0,id0,e1,id1)
            float4 v0 = sh4[__float_as_int(p.y) * 8 + li];
            float4 v1 = sh4[__float_as_int(p.w) * 8 + li];
            dn += p.x + p.z;
            acc.x = fmaf(p.x, v0.x, fmaf(p.z, v1.x, acc.x));
            acc.y = fmaf(p.x, v0.y, fmaf(p.z, v1.y, acc.y));
            acc.z = fmaf(p.x, v0.z, fmaf(p.z, v1.z, acc.z));
            acc.w = fmaf(p.x, v0.w, fmaf(p.z, v1.w, acc.w));
        }
        float inv = 1.0f / dn;
        float4 o4;
        o4.x = fmaf(acc.x, inv, bias4.x); o4.y = fmaf(acc.y, inv, bias4.y);
        o4.z = fmaf(acc.z, inv, bias4.z); o4.w = fmaf(acc.w, inv, bias4.w);
        reinterpret_cast<float4*>(
            g_out1 + ((size_t)b * kN + n0 + sub) * kD + half * 32)[li] = o4;
        ts4.x += o4.x; ts4.y += o4.y; ts4.z += o4.z; ts4.w += o4.w;
        tq4.x = fmaf(o4.x, o4.x, tq4.x); tq4.y = fmaf(o4.y, o4.y, tq4.y);
        tq4.z = fmaf(o4.z, o4.z, tq4.z); tq4.w = fmaf(o4.w, o4.w, tq4.w);
        __syncwarp();                          // WAR on sp4[wid]
    }
#pragma unroll
    for (int off = 8; off <= 16; off <<= 1) {
        ts4.x += __shfl_xor_sync(0xffffffffu, ts4.x, off);
        ts4.y += __shfl_xor_sync(0xffffffffu, ts4.y, off);
        ts4.z += __shfl_xor_sync(0xffffffffu, ts4.z, off);
        ts4.w += __shfl_xor_sync(0xffffffffu, ts4.w, off);
        tq4.x += __shfl_xor_sync(0xffffffffu, tq4.x, off);
        tq4.y += __shfl_xor_sync(0xffffffffu, tq4.y, off);
        tq4.z += __shfl_xor_sync(0xffffffffu, tq4.z, off);
        tq4.w += __shfl_xor_sync(0xffffffffu, tq4.w, off);
    }
    if (sub == 0) {
        reinterpret_cast<float4*>(&rs[wid][0])[li] = ts4;
        reinterpret_cast<float4*>(&rq[wid][0])[li] = tq4;
    }
    __syncthreads();
    if (t < 32) {
        float s = 0.f, q = 0.f;
#pragma unroll 8
        for (int w = 0; w < 32; w++) { s += rs[w][t]; q += rq[w][t]; }
        atomicAdd(&g_sum1[half * 32 + t], (double)s);
        atomicAdd(&g_ssq1[half * 32 + t], (double)q);
    }
}

// ---------------- BN affine finalize (block-level; fp64 amortized) ----------
__device__ __forceinline__ void bn_ab(int d, const float* gm, const float* bt,
                                      const double* S, const double* Q,
                                      float& a, float& b) {
    double m = S[d] / (double)kM;
    double var = Q[d] / (double)kM - m * m;
    float inv = (float)(1.0 / sqrt(var + (double)kEps));
    a = gm[d] * inv;
    b = bt[d] - (float)m * a;
}

// ---------------- kernel 5: BN2 statistics ----------------------------------
__global__ void k_stats2(const float* __restrict__ emb,
                         const float* __restrict__ g1, const float* __restrict__ b1v) {
    __shared__ float a1s[kD], b1s[kD];
    int t = threadIdx.x;
    if (t < kD) { float a, b; bn_ab(t, g1, b1v, g_sum1, g_ssq1, a, b); a1s[t] = a; b1s[t] = b; }
    __syncthreads();
    int c = t & 63, rg = t >> 6;
    float a1 = a1s[c], b1 = b1s[c];
    float ts = 0.f, tq = 0.f;
    int r0 = blockIdx.x * 64;
    for (int i = 0; i < 16; i++) {
        int r = r0 + rg * 16 + i;
        float x = g_out1[(size_t)r * kD + c];
        float y = fmaxf(fmaf(a1, x, b1), 0.f);
        float rep = y * emb[(size_t)(r & (kN - 1)) * kD + c];
        ts += rep; tq += rep * rep;
    }
    __shared__ float rs[4][kD], rq[4][kD];
    rs[rg][c] = ts; rq[rg][c] = tq;
    __syncthreads();
    if (t < kD) {
        float s = 0.f, q = 0.f;
        for (int g = 0; g < 4; g++) { s += rs[g][t]; q += rq[g][t]; }
        atomicAdd(&g_sum2[t], (double)s);
        atomicAdd(&g_ssq2[t], (double)q);
    }
}

// ---------------- kernel 6: final projection --------------------------------
__global__ void k_final(const float* __restrict__ emb, const float* __restrict__ out_w,
                        const float* __restrict__ out_b,
                        const float* __restrict__ g1, const float* __restrict__ b1v,
                        const float* __restrict__ g2, const float* __restrict__ b2v,
                        float* __restrict__ out) {
    __shared__ float aff[4][kD];
    int t = threadIdx.x, lane = t & 31;
    if (t < kD) {
        float a, b;
        bn_ab(t, g1, b1v, g_sum1, g_ssq1, a, b); aff[0][t] = a; aff[1][t] = b;
        bn_ab(t, g2, b2v, g_sum2, g_ssq2, a, b); aff[2][t] = a; aff[3][t] = b;
    }
    __syncthreads();
    int gw = (blockIdx.x * blockDim.x + t) >> 5;
    int nw = (gridDim.x * blockDim.x) >> 5;
    float a10 = aff[0][lane], b10 = aff[1][lane];
    float a11 = aff[0][lane + 32], b11 = aff[1][lane + 32];
    float a20 = aff[2][lane], b20 = aff[3][lane];
    float a21 = aff[2][lane + 32], b21 = aff[3][lane + 32];
    float w0 = out_w[lane], w1 = out_w[lane + 32];
    float ob = out_b[0];
    for (int r = gw; r < kM; r += nw) {
        int n = r & (kN - 1);
        float x0 = g_out1[(size_t)r * kD + lane];
        float x1 = g_out1[(size_t)r * kD + lane + 32];
        float y0 = fmaxf(fmaf(a10, x0, b10), 0.f) * emb[(size_t)n * kD + lane];
        float y1 = fmaxf(fmaf(a11, x1, b11), 0.f) * emb[(size_t)n * kD + lane + 32];
        float z0 = fmaxf(fmaf(a20, y0, b20), 0.f);
        float z1 = fmaxf(fmaf(a21, y1, b21), 0.f);
        float sred = z0 * w0 + z1 * w1;
#pragma unroll
        for (int o = 16; o; o >>= 1) sred += __shfl_xor_sync(0xffffffffu, sred, o);
        if (lane == 0) out[r] = sred + ob;
    }
}

// ---------------- launch ----------------------------------------------------
extern "C" void kernel_launch(void* const* d_in, const int* in_sizes, int n_in,
                              void* d_out, int out_size) {
    const float* data     = (const float*)d_in[0];
    // d_in[1] = org_edge_index (int64) — unused by the reference
    const float* emb      = (const float*)d_in[2];
    const float* lin_w    = (const float*)d_in[3];
    const float* att_i    = (const float*)d_in[4];
    const float* att_j    = (const float*)d_in[5];
    const float* aei      = (const float*)d_in[6];
    const float* aej      = (const float*)d_in[7];
    const float* gnn_bias = (const float*)d_in[8];
    const float* g1       = (const float*)d_in[9];
    const float* b1       = (const float*)d_in[10];
    const float* g2       = (const float*)d_in[11];
    const float* b2       = (const float*)d_in[12];
    const float* out_w    = (const float*)d_in[13];
    const float* out_b    = (const float*)d_in[14];
    float* out = (float*)d_out;

    cudaFuncSetAttribute(k_main, cudaFuncAttributeMaxDynamicSharedMemorySize,
                         kN * 32 * (int)sizeof(float));

    k_cos<<<dim3(16, 16), 256>>>(emb, aei, aej);
    k_h<<<2048, 256>>>(data, lin_w, att_i, att_j);
    k_topk<<<1024, 256>>>();
    k_main<<<128, 1024, kN * 32 * sizeof(float)>>>(gnn_bias);
    k_stats2<<<1024, 256>>>(emb, g1, b1);
    k_final<<<512, 256>>>(emb, out_w, out_b, g1, b1, g2, b2, out);
}

// round 14
// speedup vs baseline: 1.8324x; 1.0228x over previous
#include <cuda_runtime.h>
#include <math.h>

// Problem constants
constexpr int kB = 64, kN = 1024, kF = 16, kD = 64, kK = 20;
constexpr int kM = kB * kN;              // 65536 rows
constexpr float kEps = 1e-5f, kSlope = 0.2f;

// ---------------- scratch (device globals: allocation-free) ----------------
__device__ float  g_h[(size_t)kM * kD];      // 16 MB
__device__ float  g_out1[(size_t)kM * kD];   // 16 MB
__device__ float2 g_esi2[kM];                // {e^si, e^{0.2 si}}
__device__ float2 g_esj2[kM];                // {e^sj, e^{0.2 sj}}
__device__ float  g_emi[kN];
__device__ float  g_emj[kN];
__device__ float  g_cos[(size_t)kN * kN];    // 4 MB
__device__ int    g_idx[kN * kK];
__device__ double g_sum1[kD], g_ssq1[kD], g_sum2[kD], g_ssq2[kD];

// ---------------- kernel 1: cosine Gram + norms + emb-att dots + zeroing ----
__global__ void k_cos(const float* __restrict__ emb,
                      const float* __restrict__ aei,
                      const float* __restrict__ aej) {
    __shared__ float As[kD][68];   // row stride 272 B (16B-aligned): float4 reads
    __shared__ float Bs[kD][68];
    __shared__ float rnA[64], rnB[64];
    int t = threadIdx.x;
    int bn = blockIdx.y * 64, bm = blockIdx.x * 64;
    if (blockIdx.x == 0 && blockIdx.y == 0 && t < kD) {
        g_sum1[t] = 0.0; g_ssq1[t] = 0.0; g_sum2[t] = 0.0; g_ssq2[t] = 0.0;
    }
    for (int idx = t; idx < 64 * 64; idx += 256) {
        int r = idx >> 6, k = idx & 63;
        As[k][r] = emb[(size_t)(bn + r) * kD + k];
        Bs[k][r] = emb[(size_t)(bm + r) * kD + k];
    }
    __syncthreads();
    if (t < 64) {
        float s = 0.f;
        for (int k = 0; k < 64; k++) { float v = As[k][t]; s += v * v; }
        rnA[t] = 1.0f / sqrtf(s);
    } else if (t < 128) {
        int r = t - 64;
        float s = 0.f;
        for (int k = 0; k < 64; k++) { float v = Bs[k][r]; s += v * v; }
        rnB[r] = 1.0f / sqrtf(s);
    } else if (blockIdx.x == 0) {
        int r = (t - 128) & 63;
        const float* av = (t < 192) ? aei : aej;
        float s = 0.f;
        for (int k = 0; k < 64; k++) s += As[k][r] * av[k];
        if (t < 192) g_emi[bn + r] = s; else g_emj[bn + r] = s;
    }
    int tx = t & 15, ty = t >> 4;
    float acc[4][4] = {};
#pragma unroll 4
    for (int k = 0; k < 64; k++) {
        float4 a4 = *reinterpret_cast<const float4*>(&As[k][ty * 4]);
        float4 b4 = *reinterpret_cast<const float4*>(&Bs[k][tx * 4]);
        float a[4] = {a4.x, a4.y, a4.z, a4.w};
        float b[4] = {b4.x, b4.y, b4.z, b4.w};
#pragma unroll
        for (int i = 0; i < 4; i++)
#pragma unroll
            for (int j = 0; j < 4; j++) acc[i][j] += a[i] * b[j];
    }
    __syncthreads();
#pragma unroll
    for (int i = 0; i < 4; i++) {
        int r = bn + ty * 4 + i;
        float rn = rnA[ty * 4 + i];
#pragma unroll
        for (int j = 0; j < 4; j++) {
            int c = bm + tx * 4 + j;
            g_cos[(size_t)r * kN + c] = acc[i][j] * rn * rnB[tx * 4 + j];
        }
    }
}

// ---------------- kernel 2: h = data @ lin_w^T + exp tables -----------------
__global__ void k_h(const float* __restrict__ data, const float* __restrict__ lin_w,
                    const float* __restrict__ att_i, const float* __restrict__ att_j) {
    __shared__ float lw[kF][kD];
    for (int idx = threadIdx.x; idx < kF * kD; idx += blockDim.x) {
        int f = idx >> 6, d = idx & 63;
        lw[f][d] = lin_w[d * kF + f];
    }
    __syncthreads();
    int lane = threadIdx.x & 31;
    int gw = (blockIdx.x * blockDim.x + threadIdx.x) >> 5;
    int nw = (gridDim.x * blockDim.x) >> 5;
    float ai0 = att_i[lane], ai1 = att_i[lane + 32];
    float aj0 = att_j[lane], aj1 = att_j[lane + 32];
    for (int r = gw; r < kM; r += nw) {
        const float4* dp = reinterpret_cast<const float4*>(data + (size_t)r * kF);
        float4 q0 = dp[0], q1 = dp[1], q2 = dp[2], q3 = dp[3];
        float df[16] = {q0.x, q0.y, q0.z, q0.w, q1.x, q1.y, q1.z, q1.w,
                        q2.x, q2.y, q2.z, q2.w, q3.x, q3.y, q3.z, q3.w};
        float h0 = 0.f, h1 = 0.f;
#pragma unroll
        for (int f = 0; f < 16; f++) {
            h0 += df[f] * lw[f][lane];
            h1 += df[f] * lw[f][lane + 32];
        }
        g_h[(size_t)r * kD + lane] = h0;
        g_h[(size_t)r * kD + lane + 32] = h1;
        float si = h0 * ai0 + h1 * ai1;
        float sj = h0 * aj0 + h1 * aj1;
#pragma unroll
        for (int o = 16; o; o >>= 1) {
            si += __shfl_xor_sync(0xffffffffu, si, o);
            sj += __shfl_xor_sync(0xffffffffu, sj, o);
        }
        if (lane == 0) {
            int n = r & (kN - 1);
            float siv = si + g_emi[n], sjv = sj + g_emj[n];
            g_esi2[r] = make_float2(expf(siv), expf(0.2f * siv));
            g_esj2[r] = make_float2(expf(sjv), expf(0.2f * sjv));
        }
    }
}

// ---------------- kernel 3: top-20 radix select with candidate compaction ---
__global__ void k_topk() {
    __shared__ unsigned sv[kN];
    __shared__ int hist[256];
    __shared__ int suf[257];
    __shared__ unsigned cva[kN]; __shared__ int cia[kN];
    __shared__ unsigned cvb[kN]; __shared__ int cib[kN];
    __shared__ int s_digit, s_need, s_out, s_ca, s_cb, s_sel;
    __shared__ int wmin[8];
    int n = blockIdx.x, t = threadIdx.x;
    int lane = t & 31, wid = t >> 5;
    const unsigned* row = reinterpret_cast<const unsigned*>(g_cos + (size_t)n * kN);
#pragma unroll
    for (int i = 0; i < 4; i++) {
        unsigned x = row[t + 256 * i];
        x ^= (x & 0x80000000u) ? 0xFFFFFFFFu : 0x80000000u;  // order-preserving
        sv[t + 256 * i] = x;
    }
    hist[t] = 0;
    if (t == 0) { s_need = kK; s_out = 0; s_ca = 0; suf[256] = 0; }
    __syncthreads();
#pragma unroll
    for (int i = 0; i < 4; i++)
        atomicAdd(&hist[sv[t + 256 * i] >> 24], 1);
    __syncthreads();
    if (wid == 0) {  // suffix sums: suf[e] = count of digit >= e
        int base = 255 - 8 * lane;
        int loc[8], s = 0;
#pragma unroll
        for (int j = 0; j < 8; j++) { loc[j] = hist[base - j]; s += loc[j]; }
        int run = s;
#pragma unroll
        for (int off = 1; off < 32; off <<= 1) {
            int v = __shfl_up_sync(0xffffffffu, run, off);
            if (lane >= off) run += v;
        }
        int acc = run - s;
#pragma unroll
        for (int j = 0; j < 8; j++) { acc += loc[j]; suf[base - j] = acc; }
    }
    __syncthreads();
    {
        int need = s_need;
        if (suf[t] >= need && suf[t + 1] < need) s_digit = t;
    }
    __syncthreads();
    {
        int digit = s_digit;
        int above = suf[digit + 1];
#pragma unroll
        for (int i = 0; i < 4; i++) {
            int m = t + 256 * i;
            unsigned x = sv[m];
            int d = x >> 24;
            if (d > digit)       { int p = atomicAdd(&s_out, 1); g_idx[n * kK + p] = m; }
            else if (d == digit) { int p = atomicAdd(&s_ca, 1); cva[p] = x; cia[p] = m; }
        }
        if (t == 0) s_need = kK - above;
    }
    __syncthreads();
    unsigned* cv = cva; int* ci = cia;
    unsigned* nv = cvb; int* niv = cib;
    int C = s_ca;
    for (int shift = 16; shift >= 0; shift -= 8) {
        hist[t] = 0;
        if (t == 0) s_cb = 0;
        __syncthreads();
        for (int i = t; i < C; i += 256)
            atomicAdd(&hist[(cv[i] >> shift) & 255], 1);
        __syncthreads();
        if (wid == 0) {
            int base = 255 - 8 * lane;
            int loc[8], s = 0;
#pragma unroll
            for (int j = 0; j < 8; j++) { loc[j] = hist[base - j]; s += loc[j]; }
            int run = s;
#pragma unroll
            for (int off = 1; off < 32; off <<= 1) {
                int v = __shfl_up_sync(0xffffffffu, run, off);
                if (lane >= off) run += v;
            }
            int acc = run - s;
#pragma unroll
            for (int j = 0; j < 8; j++) { acc += loc[j]; suf[base - j] = acc; }
        }
        __syncthreads();
        int need = s_need;
        if (suf[t] >= need && suf[t + 1] < need) s_digit = t;
        __syncthreads();
        int digit = s_digit;
        int above = suf[digit + 1];
        for (int i = t; i < C; i += 256) {
            unsigned x = cv[i];
            int d = (x >> shift) & 255;
            if (d > digit)       { int p = atomicAdd(&s_out, 1); g_idx[n * kK + p] = ci[i]; }
            else if (d == digit) { int p = atomicAdd(&s_cb, 1); nv[p] = x; niv[p] = ci[i]; }
        }
        if (t == 0) s_need = need - above;
        __syncthreads();
        C = s_cb;
        unsigned* tv = cv; cv = nv; nv = tv;
        int* ti = ci; ci = niv; niv = ti;
    }
    int R = s_need;
    int base = kK - R;
    if (C == R) {
        if (t < R) g_idx[n * kK + base + t] = ci[t];
    } else {  // rare: multiplicity at threshold -> lowest indices win
        for (int r = 0; r < R; r++) {
            int best = 0x7fffffff;
            for (int i = t; i < C; i += 256) best = min(best, ci[i]);
#pragma unroll
            for (int o = 16; o; o >>= 1) best = min(best, __shfl_xor_sync(0xffffffffu, best, o));
            if (lane == 0) wmin[wid] = best;
            __syncthreads();
            if (t == 0) {
                int m = 0x7fffffff;
                for (int w = 0; w < 8; w++) m = min(m, wmin[w]);
                g_idx[n * kK + base + r] = m;
                s_sel = m;
            }
            __syncthreads();
            for (int i = t; i < C; i += 256) if (ci[i] == s_sel) ci[i] = 0x7fffffff;
            __syncthreads();
        }
    }
}

// ---------------- kernel 4: inline alpha + smem gather + BN1 stats ----------
// Double-buffered sp4: idx2 LDGs for group g+1 issue BEFORE group g's gather,
// weight fill completes after. Tile staged with float4.
__global__ void __launch_bounds__(1024, 1)
k_main(const float* __restrict__ gnn_bias) {
    extern __shared__ float sh[];              // [1024][32] = 128 KB
    __shared__ float4 sp4[2][32][40];          // 40 KB double buffer
    __shared__ float  rs[32][32], rq[32][32];  // 8 KB
    __shared__ float2 ssi[kN], ssj[kN];        // 16 KB
    int t = threadIdx.x, lane = t & 31, wid = t >> 5;
    int sub = lane >> 3, li = lane & 7;
    int b = blockIdx.x >> 1, half = blockIdx.x & 1;
    const float4* hb4 = reinterpret_cast<const float4*>(
        g_h + (size_t)b * kN * kD + half * 32);
    float4* sh4w = reinterpret_cast<float4*>(sh);
    for (int i = t; i < kN * 8; i += 1024) {   // 8192 float4 = 128 KB
        int n = i >> 3, j = i & 7;
        sh4w[i] = hb4[n * 16 + j];
    }
    for (int i = t; i < kN; i += 1024) {
        ssi[i] = g_esi2[b * kN + i];
        ssj[i] = g_esj2[b * kN + i];
    }
    __syncthreads();
    const float4* sh4 = reinterpret_cast<const float4*>(sh);
    const int2* idx2 = reinterpret_cast<const int2*>(g_idx);   // 10 int2 per row
    // per-lane fill coordinates (entry A: idx=lane; entry B: idx=32+lane, lane<8)
    int rA = lane / 10, jA = lane - rA * 10;
    int jB = lane + 2;                          // idx 32..39 -> r=3, j=lane+2
    float4 bias4 = reinterpret_cast<const float4*>(gnn_bias)[half * 8 + li];
    float4 ts4 = make_float4(0.f, 0.f, 0.f, 0.f);
    float4 tq4 = make_float4(0.f, 0.f, 0.f, 0.f);
    // ---- prologue: fill group 0 into buffer 0 ----
    {
        int n0 = wid * 4;
        int2 ids = idx2[(n0 + rA) * 10 + jA];
        float2 ei = ssi[n0 + rA];
        float2 e0 = ssj[ids.x], e1 = ssj[ids.y];
        float f0 = ei.x * e0.x, f1 = ei.x * e1.x;
        float w0 = (f0 > 1.f) ? f0 : ei.y * e0.y;
        float w1 = (f1 > 1.f) ? f1 : ei.y * e1.y;
        sp4[0][wid][lane] = make_float4(w0, __int_as_float(ids.x),
                                        w1, __int_as_float(ids.y));
        if (lane < 8) {
            int2 idsb = idx2[(n0 + 3) * 10 + jB];
            float2 eib = ssi[n0 + 3];
            float2 e0b = ssj[idsb.x], e1b = ssj[idsb.y];
            float f0b = eib.x * e0b.x, f1b = eib.x * e1b.x;
            float w0b = (f0b > 1.f) ? f0b : eib.y * e0b.y;
            float w1b = (f1b > 1.f) ? f1b : eib.y * e1b.y;
            sp4[0][wid][32 + lane] = make_float4(w0b, __int_as_float(idsb.x),
                                                 w1b, __int_as_float(idsb.y));
        }
    }
    __syncwarp();
    int pb = 0;
#pragma unroll 1
    for (int g = 0; g < 8; g++) {
        int n0 = (g * 32 + wid) * 4;
        // ---- prefetch next group's indices (LDG issues now, used later) ----
        int2 pA = make_int2(0, 0), pB = make_int2(0, 0);
        int n0n = ((g + 1) * 32 + wid) * 4;
        if (g < 7) {
            pA = idx2[(n0n + rA) * 10 + jA];
            if (lane < 8) pB = idx2[(n0n + 3) * 10 + jB];
        }
        // ---- gather group g ----
        float4 acc = make_float4(0.f, 0.f, 0.f, 0.f);
        float dn = 0.f;
#pragma unroll
        for (int k2 = 0; k2 < kK / 2; k2++) {
            float4 p = sp4[pb][wid][sub * 10 + k2];   // (e0,id0,e1,id1)
            float4 v0 = sh4[__float_as_int(p.y) * 8 + li];
            float4 v1 = sh4[__float_as_int(p.w) * 8 + li];
            dn += p.x + p.z;
            acc.x = fmaf(p.x, v0.x, fmaf(p.z, v1.x, acc.x));
            acc.y = fmaf(p.x, v0.y, fmaf(p.z, v1.y, acc.y));
            acc.z = fmaf(p.x, v0.z, fmaf(p.z, v1.z, acc.z));
            acc.w = fmaf(p.x, v0.w, fmaf(p.z, v1.w, acc.w));
        }
        float inv = 1.0f / dn;
        float4 o4;
        o4.x = fmaf(acc.x, inv, bias4.x); o4.y = fmaf(acc.y, inv, bias4.y);
        o4.z = fmaf(acc.z, inv, bias4.z); o4.w = fmaf(acc.w, inv, bias4.w);
        reinterpret_cast<float4*>(
            g_out1 + ((size_t)b * kN + n0 + sub) * kD + half * 32)[li] = o4;
        ts4.x += o4.x; ts4.y += o4.y; ts4.z += o4.z; ts4.w += o4.w;
        tq4.x = fmaf(o4.x, o4.x, tq4.x); tq4.y = fmaf(o4.y, o4.y, tq4.y);
        tq4.z = fmaf(o4.z, o4.z, tq4.z); tq4.w = fmaf(o4.w, o4.w, tq4.w);
        // ---- complete fill of group g+1 into the other buffer ----
        if (g < 7) {
            float2 ei = ssi[n0n + rA];
            float2 e0 = ssj[pA.x], e1 = ssj[pA.y];
            float f0 = ei.x * e0.x, f1 = ei.x * e1.x;
            float w0 = (f0 > 1.f) ? f0 : ei.y * e0.y;
            float w1 = (f1 > 1.f) ? f1 : ei.y * e1.y;
            sp4[pb ^ 1][wid][lane] = make_float4(w0, __int_as_float(pA.x),
                                                 w1, __int_as_float(pA.y));
            if (lane < 8) {
                float2 eib = ssi[n0n + 3];
                float2 e0b = ssj[pB.x], e1b = ssj[pB.y];
                float f0b = eib.x * e0b.x, f1b = eib.x * e1b.x;
                float w0b = (f0b > 1.f) ? f0b : eib.y * e0b.y;
                float w1b = (f1b > 1.f) ? f1b : eib.y * e1b.y;
                sp4[pb ^ 1][wid][32 + lane] = make_float4(w0b, __int_as_float(pB.x),
                                                          w1b, __int_as_float(pB.y));
            }
        }
        __syncwarp();
        pb ^= 1;
    }
#pragma unroll
    for (int off = 8; off <= 16; off <<= 1) {
        ts4.x += __shfl_xor_sync(0xffffffffu, ts4.x, off);
        ts4.y += __shfl_xor_sync(0xffffffffu, ts4.y, off);
        ts4.z += __shfl_xor_sync(0xffffffffu, ts4.z, off);
        ts4.w += __shfl_xor_sync(0xffffffffu, ts4.w, off);
        tq4.x += __shfl_xor_sync(0xffffffffu, tq4.x, off);
        tq4.y += __shfl_xor_sync(0xffffffffu, tq4.y, off);
        tq4.z += __shfl_xor_sync(0xffffffffu, tq4.z, off);
        tq4.w += __shfl_xor_sync(0xffffffffu, tq4.w, off);
    }
    if (sub == 0) {
        reinterpret_cast<float4*>(&rs[wid][0])[li] = ts4;
        reinterpret_cast<float4*>(&rq[wid][0])[li] = tq4;
    }
    __syncthreads();
    if (t < 32) {
        float s = 0.f, q = 0.f;
#pragma unroll 8
        for (int w = 0; w < 32; w++) { s += rs[w][t]; q += rq[w][t]; }
        atomicAdd(&g_sum1[half * 32 + t], (double)s);
        atomicAdd(&g_ssq1[half * 32 + t], (double)q);
    }
}

// ---------------- BN affine finalize (block-level; fp64 amortized) ----------
__device__ __forceinline__ void bn_ab(int d, const float* gm, const float* bt,
                                      const double* S, const double* Q,
                                      float& a, float& b) {
    double m = S[d] / (double)kM;
    double var = Q[d] / (double)kM - m * m;
    float inv = (float)(1.0 / sqrt(var + (double)kEps));
    a = gm[d] * inv;
    b = bt[d] - (float)m * a;
}

// ---------------- kernel 5: BN2 statistics (float4 path) --------------------
__global__ void k_stats2(const float* __restrict__ emb,
                         const float* __restrict__ g1, const float* __restrict__ b1v) {
    __shared__ float a1s[kD], b1s[kD];
    __shared__ float4 rs[16][16], rq[16][16];
    int t = threadIdx.x;
    if (t < kD) { float a, b; bn_ab(t, g1, b1v, g_sum1, g_ssq1, a, b); a1s[t] = a; b1s[t] = b; }
    __syncthreads();
    int q16 = t & 15, rg = t >> 4;
    float4 a1 = *reinterpret_cast<const float4*>(&a1s[q16 * 4]);
    float4 b1 = *reinterpret_cast<const float4*>(&b1s[q16 * 4]);
    const float4* o14 = reinterpret_cast<const float4*>(g_out1);
    const float4* em4 = reinterpret_cast<const float4*>(emb);
    float4 ts = make_float4(0.f, 0.f, 0.f, 0.f);
    float4 tq = make_float4(0.f, 0.f, 0.f, 0.f);
    int r0 = blockIdx.x * 64;
#pragma unroll
    for (int i = 0; i < 4; i++) {
        int r = r0 + i * 16 + rg;
        float4 x = o14[(size_t)r * 16 + q16];
        float4 e = em4[(size_t)(r & (kN - 1)) * 16 + q16];
        float y0 = fmaxf(fmaf(a1.x, x.x, b1.x), 0.f) * e.x;
        float y1 = fmaxf(fmaf(a1.y, x.y, b1.y), 0.f) * e.y;
        float y2 = fmaxf(fmaf(a1.z, x.z, b1.z), 0.f) * e.z;
        float y3 = fmaxf(fmaf(a1.w, x.w, b1.w), 0.f) * e.w;
        ts.x += y0; ts.y += y1; ts.z += y2; ts.w += y3;
        tq.x = fmaf(y0, y0, tq.x); tq.y = fmaf(y1, y1, tq.y);
        tq.z = fmaf(y2, y2, tq.z); tq.w = fmaf(y3, y3, tq.w);
    }
    rs[rg][q16] = ts; rq[rg][q16] = tq;
    __syncthreads();
    if (t < kD) {
        int c4 = t >> 2, cc = t & 3;
        float s = 0.f, q = 0.f;
#pragma unroll
        for (int g = 0; g < 16; g++) {
            const float* pr = reinterpret_cast<const float*>(&rs[g][c4]);
            const float* pq = reinterpret_cast<const float*>(&rq[g][c4]);
            s += pr[cc]; q += pq[cc];
        }
        atomicAdd(&g_sum2[t], (double)s);
        atomicAdd(&g_ssq2[t], (double)q);
    }
}

// ---------------- kernel 6: final projection (half-warp per row, float4) ----
__global__ void k_final(const float* __restrict__ emb, const float* __restrict__ out_w,
                        const float* __restrict__ out_b,
                        const float* __restrict__ g1, const float* __restrict__ b1v,
                        const float* __restrict__ g2, const float* __restrict__ b2v,
                        float* __restrict__ out) {
    __shared__ float aff[4][kD];
    __shared__ float ws[kD];
    int t = threadIdx.x, lane = t & 31;
    if (t < kD) {
        float a, b;
        bn_ab(t, g1, b1v, g_sum1, g_ssq1, a, b); aff[0][t] = a; aff[1][t] = b;
        bn_ab(t, g2, b2v, g_sum2, g_ssq2, a, b); aff[2][t] = a; aff[3][t] = b;
        ws[t] = out_w[t];
    }
    __syncthreads();
    int h = lane >> 4, q16 = lane & 15;
    float4 a1 = *reinterpret_cast<const float4*>(&aff[0][q16 * 4]);
    float4 b1 = *reinterpret_cast<const float4*>(&aff[1][q16 * 4]);
    float4 a2 = *reinterpret_cast<const float4*>(&aff[2][q16 * 4]);
    float4 b2 = *reinterpret_cast<const float4*>(&aff[3][q16 * 4]);
    float4 w4 = *reinterpret_cast<const float4*>(&ws[q16 * 4]);
    float ob = out_b[0];
    const float4* o14 = reinterpret_cast<const float4*>(g_out1);
    const float4* em4 = reinterpret_cast<const float4*>(emb);
    int gw = (blockIdx.x * blockDim.x + t) >> 5;
    int nw = (gridDim.x * blockDim.x) >> 5;
    for (int rp = gw; rp < kM / 2; rp += nw) {
        int r = rp * 2 + h;
        int n = r & (kN - 1);
        float4 x = o14[(size_t)r * 16 + q16];
        float4 e = em4[(size_t)n * 16 + q16];
        float y0 = fmaxf(fmaf(a1.x, x.x, b1.x), 0.f) * e.x;
        float y1 = fmaxf(fmaf(a1.y, x.y, b1.y), 0.f) * e.y;
        float y2 = fmaxf(fmaf(a1.z, x.z, b1.z), 0.f) * e.z;
        float y3 = fmaxf(fmaf(a1.w, x.w, b1.w), 0.f) * e.w;
        float s = fmaxf(fmaf(a2.x, y0, b2.x), 0.f) * w4.x
                + fmaxf(fmaf(a2.y, y1, b2.y), 0.f) * w4.y
                + fmaxf(fmaf(a2.z, y2, b2.z), 0.f) * w4.z
                + fmaxf(fmaf(a2.w, y3, b2.w), 0.f) * w4.w;
#pragma unroll
        for (int o = 8; o; o >>= 1) s += __shfl_xor_sync(0xffffffffu, s, o);
        if (q16 == 0) out[r] = s + ob;
    }
}

// ---------------- launch ----------------------------------------------------
extern "C" void kernel_launch(void* const* d_in, const int* in_sizes, int n_in,
                              void* d_out, int out_size) {
    const float* data     = (const float*)d_in[0];
    // d_in[1] = org_edge_index (int64) — unused by the reference
    const float* emb      = (const float*)d_in[2];
    const float* lin_w    = (const float*)d_in[3];
    const float* att_i    = (const float*)d_in[4];
    const float* att_j    = (const float*)d_in[5];
    const float* aei      = (const float*)d_in[6];
    const float* aej      = (const float*)d_in[7];
    const float* gnn_bias = (const float*)d_in[8];
    const float* g1       = (const float*)d_in[9];
    const float* b1       = (const float*)d_in[10];
    const float* g2       = (const float*)d_in[11];
    const float* b2       = (const float*)d_in[12];
    const float* out_w    = (const float*)d_in[13];
    const float* out_b    = (const float*)d_in[14];
    float* out = (float*)d_out;

    cudaFuncSetAttribute(k_main, cudaFuncAttributeMaxDynamicSharedMemorySize,
                         kN * 32 * (int)sizeof(float));

    k_cos<<<dim3(16, 16), 256>>>(emb, aei, aej);
    k_h<<<2048, 256>>>(data, lin_w, att_i, att_j);
    k_topk<<<1024, 256>>>();
    k_main<<<128, 1024, kN * 32 * sizeof(float)>>>(gnn_bias);
    k_stats2<<<1024, 256>>>(emb, g1, b1);
    k_final<<<512, 256>>>(emb, out_w, out_b, g1, b1, g2, b2, out);
}

// round 16
// speedup vs baseline: 1.9161x; 1.0457x over previous
#include <cuda_runtime.h>
#include <math.h>

// Problem constants
constexpr int kB = 64, kN = 1024, kF = 16, kD = 64, kK = 20;
constexpr int kM = kB * kN;              // 65536 rows
constexpr float kEps = 1e-5f, kSlope = 0.2f;

// ---------------- scratch (device globals: allocation-free) ----------------
__device__ float  g_h[(size_t)kM * kD];      // 16 MB
__device__ float  g_out1[(size_t)kM * kD];   // 16 MB
__device__ float2 g_esi2[kM];                // {e^si, e^{0.2 si}}
__device__ float2 g_esj2[kM];                // {e^sj, e^{0.2 sj}}
__device__ float  g_cos[(size_t)kN * kN];    // 4 MB
__device__ int    g_idx[kN * kK];
__device__ double g_sum1[kD], g_ssq1[kD], g_sum2[kD], g_ssq2[kD];

// ---------------- kernel 1: FUSED cosine-Gram (blocks 0..255) +
//                  h/exp-tables (blocks 256..767) -----------------------------
// The emb@att_em_{i,j} terms fold into the h-part's warp reduction, so the
// h blocks have no dependency on the cos blocks.
__global__ void k_fused1(const float* __restrict__ emb,
                         const float* __restrict__ aei,
                         const float* __restrict__ aej,
                         const float* __restrict__ data,
                         const float* __restrict__ lin_w,
                         const float* __restrict__ att_i,
                         const float* __restrict__ att_j) {
    __shared__ float As[kD][68];   // cos part (row stride 272B, float4-aligned)
    __shared__ float Bs[kD][68];
    __shared__ float rnA[64], rnB[64];
    __shared__ float lw[kF][kD];   // h part
    int t = threadIdx.x;
    if (blockIdx.x < 256) {
        // ================= cos part =================
        int bn = (blockIdx.x >> 4) * 64, bm = (blockIdx.x & 15) * 64;
        if (blockIdx.x == 0 && t < kD) {
            g_sum1[t] = 0.0; g_ssq1[t] = 0.0; g_sum2[t] = 0.0; g_ssq2[t] = 0.0;
        }
        for (int idx = t; idx < 64 * 64; idx += 256) {
            int r = idx >> 6, k = idx & 63;
            As[k][r] = emb[(size_t)(bn + r) * kD + k];
            Bs[k][r] = emb[(size_t)(bm + r) * kD + k];
        }
        __syncthreads();
        if (t < 64) {
            float s = 0.f;
            for (int k = 0; k < 64; k++) { float v = As[k][t]; s += v * v; }
            rnA[t] = 1.0f / sqrtf(s);
        } else if (t < 128) {
            int r = t - 64;
            float s = 0.f;
            for (int k = 0; k < 64; k++) { float v = Bs[k][r]; s += v * v; }
            rnB[r] = 1.0f / sqrtf(s);
        }
        int tx = t & 15, ty = t >> 4;
        float acc[4][4] = {};
#pragma unroll 4
        for (int k = 0; k < 64; k++) {
            float4 a4 = *reinterpret_cast<const float4*>(&As[k][ty * 4]);
            float4 b4 = *reinterpret_cast<const float4*>(&Bs[k][tx * 4]);
            float a[4] = {a4.x, a4.y, a4.z, a4.w};
            float b[4] = {b4.x, b4.y, b4.z, b4.w};
#pragma unroll
            for (int i = 0; i < 4; i++)
#pragma unroll
                for (int j = 0; j < 4; j++) acc[i][j] += a[i] * b[j];
        }
        __syncthreads();
#pragma unroll
        for (int i = 0; i < 4; i++) {
            int r = bn + ty * 4 + i;
            float rn = rnA[ty * 4 + i];
#pragma unroll
            for (int j = 0; j < 4; j++) {
                int c = bm + tx * 4 + j;
                g_cos[(size_t)r * kN + c] = acc[i][j] * rn * rnB[tx * 4 + j];
            }
        }
    } else {
        // ================= h part =================
        for (int idx = t; idx < kF * kD; idx += 256) {
            int f = idx >> 6, d = idx & 63;
            lw[f][d] = lin_w[d * kF + f];
        }
        __syncthreads();
        int lane = t & 31, wid = t >> 5;
        int gw = (blockIdx.x - 256) * 8 + wid;          // 0..4095
        float ai0 = att_i[lane], ai1 = att_i[lane + 32];
        float aj0 = att_j[lane], aj1 = att_j[lane + 32];
        float ei0 = aei[lane],   ei1 = aei[lane + 32];
        float ej0 = aej[lane],   ej1 = aej[lane + 32];
        for (int r = gw; r < kM; r += 4096) {
            const float4* dp = reinterpret_cast<const float4*>(data + (size_t)r * kF);
            float4 q0 = dp[0], q1 = dp[1], q2 = dp[2], q3 = dp[3];
            float df[16] = {q0.x, q0.y, q0.z, q0.w, q1.x, q1.y, q1.z, q1.w,
                            q2.x, q2.y, q2.z, q2.w, q3.x, q3.y, q3.z, q3.w};
            float h0 = 0.f, h1 = 0.f;
#pragma unroll
            for (int f = 0; f < 16; f++) {
                h0 += df[f] * lw[f][lane];
                h1 += df[f] * lw[f][lane + 32];
            }
            g_h[(size_t)r * kD + lane] = h0;
            g_h[(size_t)r * kD + lane + 32] = h1;
            int n = r & (kN - 1);
            float e0 = emb[(size_t)n * kD + lane];
            float e1 = emb[(size_t)n * kD + lane + 32];
            float vi = h0 * ai0 + h1 * ai1 + e0 * ei0 + e1 * ei1;
            float vj = h0 * aj0 + h1 * aj1 + e0 * ej0 + e1 * ej1;
#pragma unroll
            for (int o = 16; o; o >>= 1) {
                vi += __shfl_xor_sync(0xffffffffu, vi, o);
                vj += __shfl_xor_sync(0xffffffffu, vj, o);
            }
            if (lane == 0) {
                g_esi2[r] = make_float2(expf(vi), expf(0.2f * vi));
                g_esj2[r] = make_float2(expf(vj), expf(0.2f * vj));
            }
        }
    }
}

// ---------------- kernel 2: top-20 radix select with candidate compaction ---
__global__ void k_topk() {
    __shared__ unsigned sv[kN];
    __shared__ int hist[256];
    __shared__ int suf[257];
    __shared__ unsigned cva[kN]; __shared__ int cia[kN];
    __shared__ unsigned cvb[kN]; __shared__ int cib[kN];
    __shared__ int s_digit, s_need, s_out, s_ca, s_cb, s_sel;
    __shared__ int wmin[8];
    int n = blockIdx.x, t = threadIdx.x;
    int lane = t & 31, wid = t >> 5;
    const uint4* row4 = reinterpret_cast<const uint4*>(g_cos + (size_t)n * kN);
    {
        uint4 x = row4[t];
        uint4 y;
        y.x = x.x ^ ((x.x & 0x80000000u) ? 0xFFFFFFFFu : 0x80000000u);
        y.y = x.y ^ ((x.y & 0x80000000u) ? 0xFFFFFFFFu : 0x80000000u);
        y.z = x.z ^ ((x.z & 0x80000000u) ? 0xFFFFFFFFu : 0x80000000u);
        y.w = x.w ^ ((x.w & 0x80000000u) ? 0xFFFFFFFFu : 0x80000000u);
        reinterpret_cast<uint4*>(sv)[t] = y;   // sv[4t..4t+3] = cols 4t..4t+3
    }
    hist[t] = 0;
    if (t == 0) { s_need = kK; s_out = 0; s_ca = 0; suf[256] = 0; }
    __syncthreads();
#pragma unroll
    for (int i = 0; i < 4; i++)
        atomicAdd(&hist[sv[t + 256 * i] >> 24], 1);
    __syncthreads();
    if (wid == 0) {  // suffix sums: suf[e] = count of digit >= e
        int base = 255 - 8 * lane;
        int loc[8], s = 0;
#pragma unroll
        for (int j = 0; j < 8; j++) { loc[j] = hist[base - j]; s += loc[j]; }
        int run = s;
#pragma unroll
        for (int off = 1; off < 32; off <<= 1) {
            int v = __shfl_up_sync(0xffffffffu, run, off);
            if (lane >= off) run += v;
        }
        int acc = run - s;
#pragma unroll
        for (int j = 0; j < 8; j++) { acc += loc[j]; suf[base - j] = acc; }
    }
    __syncthreads();
    {
        int need = s_need;
        if (suf[t] >= need && suf[t + 1] < need) s_digit = t;
    }
    __syncthreads();
    {
        int digit = s_digit;
        int above = suf[digit + 1];
#pragma unroll
        for (int i = 0; i < 4; i++) {
            int m = t + 256 * i;
            unsigned x = sv[m];
            int d = x >> 24;
            if (d > digit)       { int p = atomicAdd(&s_out, 1); g_idx[n * kK + p] = m; }
            else if (d == digit) { int p = atomicAdd(&s_ca, 1); cva[p] = x; cia[p] = m; }
        }
        if (t == 0) s_need = kK - above;
    }
    __syncthreads();
    unsigned* cv = cva; int* ci = cia;
    unsigned* nv = cvb; int* niv = cib;
    int C = s_ca;
    for (int shift = 16; shift >= 0; shift -= 8) {
        hist[t] = 0;
        if (t == 0) s_cb = 0;
        __syncthreads();
        for (int i = t; i < C; i += 256)
            atomicAdd(&hist[(cv[i] >> shift) & 255], 1);
        __syncthreads();
        if (wid == 0) {
            int base = 255 - 8 * lane;
            int loc[8], s = 0;
#pragma unroll
            for (int j = 0; j < 8; j++) { loc[j] = hist[base - j]; s += loc[j]; }
            int run = s;
#pragma unroll
            for (int off = 1; off < 32; off <<= 1) {
                int v = __shfl_up_sync(0xffffffffu, run, off);
                if (lane >= off) run += v;
            }
            int acc = run - s;
#pragma unroll
            for (int j = 0; j < 8; j++) { acc += loc[j]; suf[base - j] = acc; }
        }
        __syncthreads();
        int need = s_need;
        if (suf[t] >= need && suf[t + 1] < need) s_digit = t;
        __syncthreads();
        int digit = s_digit;
        int above = suf[digit + 1];
        for (int i = t; i < C; i += 256) {
            unsigned x = cv[i];
            int d = (x >> shift) & 255;
            if (d > digit)       { int p = atomicAdd(&s_out, 1); g_idx[n * kK + p] = ci[i]; }
            else if (d == digit) { int p = atomicAdd(&s_cb, 1); nv[p] = x; niv[p] = ci[i]; }
        }
        if (t == 0) s_need = need - above;
        __syncthreads();
        C = s_cb;
        unsigned* tv = cv; cv = nv; nv = tv;
        int* ti = ci; ci = niv; niv = ti;
    }
    int R = s_need;
    int base = kK - R;
    if (C == R) {
        if (t < R) g_idx[n * kK + base + t] = ci[t];
    } else {  // rare: multiplicity at threshold -> lowest indices win
        for (int r = 0; r < R; r++) {
            int best = 0x7fffffff;
            for (int i = t; i < C; i += 256) best = min(best, ci[i]);
#pragma unroll
            for (int o = 16; o; o >>= 1) best = min(best, __shfl_xor_sync(0xffffffffu, best, o));
            if (lane == 0) wmin[wid] = best;
            __syncthreads();
            if (t == 0) {
                int m = 0x7fffffff;
                for (int w = 0; w < 8; w++) m = min(m, wmin[w]);
                g_idx[n * kK + base + r] = m;
                s_sel = m;
            }
            __syncthreads();
            for (int i = t; i < C; i += 256) if (ci[i] == s_sel) ci[i] = 0x7fffffff;
            __syncthreads();
        }
    }
}

// ---------------- kernel 3: inline alpha + smem gather + BN1 stats ----------
// Dual accumulator chains (even/odd k2) halve the FMA dependency depth so the
// warp keeps more LDS wavefronts in flight.
__global__ void __launch_bounds__(1024, 1)
k_main(const float* __restrict__ gnn_bias) {
    extern __shared__ float sh[];              // [1024][32] = 128 KB
    __shared__ float4 sp4[32][40];             // 20 KB
    __shared__ float  rs[32][32], rq[32][32];  // 8 KB
    __shared__ float2 ssi[kN], ssj[kN];        // 16 KB
    int t = threadIdx.x, lane = t & 31, wid = t >> 5;
    int sub = lane >> 3, li = lane & 7;
    int b = blockIdx.x >> 1, half = blockIdx.x & 1;
    const float4* hb4 = reinterpret_cast<const float4*>(
        g_h + (size_t)b * kN * kD + half * 32);
    float4* sh4w = reinterpret_cast<float4*>(sh);
    for (int i = t; i < kN * 8; i += 1024) {   // 8192 float4 = 128 KB
        int n = i >> 3, j = i & 7;
        sh4w[i] = hb4[n * 16 + j];
    }
    for (int i = t; i < kN; i += 1024) {
        ssi[i] = g_esi2[b * kN + i];
        ssj[i] = g_esj2[b * kN + i];
    }
    __syncthreads();
    const float4* sh4 = reinterpret_cast<const float4*>(sh);
    const int2* idx2 = reinterpret_cast<const int2*>(g_idx);   // 10 int2 per row
    float4 bias4 = reinterpret_cast<const float4*>(gnn_bias)[half * 8 + li];
    float4 ts4 = make_float4(0.f, 0.f, 0.f, 0.f);
    float4 tq4 = make_float4(0.f, 0.f, 0.f, 0.f);
#pragma unroll 1
    for (int g = 0; g < 8; g++) {
        int n0 = (g * 32 + wid) * 4;
#pragma unroll
        for (int pass = 0; pass < 2; pass++) {
            int idx = lane + pass * 32;
            if (idx < 40) {
                int r = idx / 10, j = idx - r * 10;
                int n = n0 + r;
                int2 ids = idx2[n * 10 + j];
                float2 ei = ssi[n];
                float2 e0 = ssj[ids.x], e1 = ssj[ids.y];
                float f0 = ei.x * e0.x, f1 = ei.x * e1.x;
                float w0 = (f0 > 1.f) ? f0 : ei.y * e0.y;
                float w1 = (f1 > 1.f) ? f1 : ei.y * e1.y;
                sp4[wid][idx] = make_float4(w0, __int_as_float(ids.x),
                                            w1, __int_as_float(ids.y));
            }
        }
        __syncwarp();
        float4 accA = make_float4(0.f, 0.f, 0.f, 0.f);
        float4 accB = make_float4(0.f, 0.f, 0.f, 0.f);
        float dnA = 0.f, dnB = 0.f;
#pragma unroll
        for (int k2 = 0; k2 < kK / 2; k2 += 2) {
            float4 p = sp4[wid][sub * 10 + k2];       // (e0,id0,e1,id1)
            float4 q = sp4[wid][sub * 10 + k2 + 1];
            float4 v0 = sh4[__float_as_int(p.y) * 8 + li];
            float4 v1 = sh4[__float_as_int(p.w) * 8 + li];
            float4 u0 = sh4[__float_as_int(q.y) * 8 + li];
            float4 u1 = sh4[__float_as_int(q.w) * 8 + li];
            dnA += p.x + p.z;
            dnB += q.x + q.z;
            accA.x = fmaf(p.x, v0.x, fmaf(p.z, v1.x, accA.x));
            accA.y = fmaf(p.x, v0.y, fmaf(p.z, v1.y, accA.y));
            accA.z = fmaf(p.x, v0.z, fmaf(p.z, v1.z, accA.z));
            accA.w = fmaf(p.x, v0.w, fmaf(p.z, v1.w, accA.w));
            accB.x = fmaf(q.x, u0.x, fmaf(q.z, u1.x, accB.x));
            accB.y = fmaf(q.x, u0.y, fmaf(q.z, u1.y, accB.y));
            accB.z = fmaf(q.x, u0.z, fmaf(q.z, u1.z, accB.z));
            accB.w = fmaf(q.x, u0.w, fmaf(q.z, u1.w, accB.w));
        }
        float inv = 1.0f / (dnA + dnB);
        float4 o4;
        o4.x = fmaf(accA.x + accB.x, inv, bias4.x);
        o4.y = fmaf(accA.y + accB.y, inv, bias4.y);
        o4.z = fmaf(accA.z + accB.z, inv, bias4.z);
        o4.w = fmaf(accA.w + accB.w, inv, bias4.w);
        reinterpret_cast<float4*>(
            g_out1 + ((size_t)b * kN + n0 + sub) * kD + half * 32)[li] = o4;
        ts4.x += o4.x; ts4.y += o4.y; ts4.z += o4.z; ts4.w += o4.w;
        tq4.x = fmaf(o4.x, o4.x, tq4.x); tq4.y = fmaf(o4.y, o4.y, tq4.y);
        tq4.z = fmaf(o4.z, o4.z, tq4.z); tq4.w = fmaf(o4.w, o4.w, tq4.w);
        __syncwarp();                          // WAR on sp4[wid]
    }
#pragma unroll
    for (int off = 8; off <= 16; off <<= 1) {
        ts4.x += __shfl_xor_sync(0xffffffffu, ts4.x, off);
        ts4.y += __shfl_xor_sync(0xffffffffu, ts4.y, off);
        ts4.z += __shfl_xor_sync(0xffffffffu, ts4.z, off);
        ts4.w += __shfl_xor_sync(0xffffffffu, ts4.w, off);
        tq4.x += __shfl_xor_sync(0xffffffffu, tq4.x, off);
        tq4.y += __shfl_xor_sync(0xffffffffu, tq4.y, off);
        tq4.z += __shfl_xor_sync(0xffffffffu, tq4.z, off);
        tq4.w += __shfl_xor_sync(0xffffffffu, tq4.w, off);
    }
    if (sub == 0) {
        reinterpret_cast<float4*>(&rs[wid][0])[li] = ts4;
        reinterpret_cast<float4*>(&rq[wid][0])[li] = tq4;
    }
    __syncthreads();
    if (t < 32) {
        float s = 0.f, q = 0.f;
#pragma unroll 8
        for (int w = 0; w < 32; w++) { s += rs[w][t]; q += rq[w][t]; }
        atomicAdd(&g_sum1[half * 32 + t], (double)s);
        atomicAdd(&g_ssq1[half * 32 + t], (double)q);
    }
}

// ---------------- BN affine finalize (block-level; fp64 amortized) ----------
__device__ __forceinline__ void bn_ab(int d, const float* gm, const float* bt,
                                      const double* S, const double* Q,
                                      float& a, float& b) {
    double m = S[d] / (double)kM;
    double var = Q[d] / (double)kM - m * m;
    float inv = (float)(1.0 / sqrt(var + (double)kEps));
    a = gm[d] * inv;
    b = bt[d] - (float)m * a;
}

// ---------------- kernel 4: BN2 statistics (float4 path) --------------------
__global__ void k_stats2(const float* __restrict__ emb,
                         const float* __restrict__ g1, const float* __restrict__ b1v) {
    __shared__ float a1s[kD], b1s[kD];
    __shared__ float4 rs[16][16], rq[16][16];
    int t = threadIdx.x;
    if (t < kD) { float a, b; bn_ab(t, g1, b1v, g_sum1, g_ssq1, a, b); a1s[t] = a; b1s[t] = b; }
    __syncthreads();
    int q16 = t & 15, rg = t >> 4;
    float4 a1 = *reinterpret_cast<const float4*>(&a1s[q16 * 4]);
    float4 b1 = *reinterpret_cast<const float4*>(&b1s[q16 * 4]);
    const float4* o14 = reinterpret_cast<const float4*>(g_out1);
    const float4* em4 = reinterpret_cast<const float4*>(emb);
    float4 ts = make_float4(0.f, 0.f, 0.f, 0.f);
    float4 tq = make_float4(0.f, 0.f, 0.f, 0.f);
    int r0 = blockIdx.x * 64;
#pragma unroll
    for (int i = 0; i < 4; i++) {
        int r = r0 + i * 16 + rg;
        float4 x = o14[(size_t)r * 16 + q16];
        float4 e = em4[(size_t)(r & (kN - 1)) * 16 + q16];
        float y0 = fmaxf(fmaf(a1.x, x.x, b1.x), 0.f) * e.x;
        float y1 = fmaxf(fmaf(a1.y, x.y, b1.y), 0.f) * e.y;
        float y2 = fmaxf(fmaf(a1.z, x.z, b1.z), 0.f) * e.z;
        float y3 = fmaxf(fmaf(a1.w, x.w, b1.w), 0.f) * e.w;
        ts.x += y0; ts.y += y1; ts.z += y2; ts.w += y3;
        tq.x = fmaf(y0, y0, tq.x); tq.y = fmaf(y1, y1, tq.y);
        tq.z = fmaf(y2, y2, tq.z); tq.w = fmaf(y3, y3, tq.w);
    }
    rs[rg][q16] = ts; rq[rg][q16] = tq;
    __syncthreads();
    if (t < kD) {
        int c4 = t >> 2, cc = t & 3;
        float s = 0.f, q = 0.f;
#pragma unroll
        for (int g = 0; g < 16; g++) {
            const float* pr = reinterpret_cast<const float*>(&rs[g][c4]);
            const float* pq = reinterpret_cast<const float*>(&rq[g][c4]);
            s += pr[cc]; q += pq[cc];
        }
        atomicAdd(&g_sum2[t], (double)s);
        atomicAdd(&g_ssq2[t], (double)q);
    }
}

// ---------------- kernel 5: final projection (half-warp per row, float4) ----
__global__ void k_final(const float* __restrict__ emb, const float* __restrict__ out_w,
                        const float* __restrict__ out_b,
                        const float* __restrict__ g1, const float* __restrict__ b1v,
                        const float* __restrict__ g2, const float* __restrict__ b2v,
                        float* __restrict__ out) {
    __shared__ float aff[4][kD];
    __shared__ float ws[kD];
    int t = threadIdx.x, lane = t & 31;
    if (t < kD) {
        float a, b;
        bn_ab(t, g1, b1v, g_sum1, g_ssq1, a, b); aff[0][t] = a; aff[1][t] = b;
        bn_ab(t, g2, b2v, g_sum2, g_ssq2, a, b); aff[2][t] = a; aff[3][t] = b;
        ws[t] = out_w[t];
    }
    __syncthreads();
    int h = lane >> 4, q16 = lane & 15;
    float4 a1 = *reinterpret_cast<const float4*>(&aff[0][q16 * 4]);
    float4 b1 = *reinterpret_cast<const float4*>(&aff[1][q16 * 4]);
    float4 a2 = *reinterpret_cast<const float4*>(&aff[2][q16 * 4]);
    float4 b2 = *reinterpret_cast<const float4*>(&aff[3][q16 * 4]);
    float4 w4 = *reinterpret_cast<const float4*>(&ws[q16 * 4]);
    float ob = out_b[0];
    const float4* o14 = reinterpret_cast<const float4*>(g_out1);
    const float4* em4 = reinterpret_cast<const float4*>(emb);
    int gw = (blockIdx.x * blockDim.x + t) >> 5;
    int nw = (gridDim.x * blockDim.x) >> 5;
    for (int rp = gw; rp < kM / 2; rp += nw) {
        int r = rp * 2 + h;
        int n = r & (kN - 1);
        float4 x = o14[(size_t)r * 16 + q16];
        float4 e = em4[(size_t)n * 16 + q16];
        float y0 = fmaxf(fmaf(a1.x, x.x, b1.x), 0.f) * e.x;
        float y1 = fmaxf(fmaf(a1.y, x.y, b1.y), 0.f) * e.y;
        float y2 = fmaxf(fmaf(a1.z, x.z, b1.z), 0.f) * e.z;
        float y3 = fmaxf(fmaf(a1.w, x.w, b1.w), 0.f) * e.w;
        float s = fmaxf(fmaf(a2.x, y0, b2.x), 0.f) * w4.x
                + fmaxf(fmaf(a2.y, y1, b2.y), 0.f) * w4.y
                + fmaxf(fmaf(a2.z, y2, b2.z), 0.f) * w4.z
                + fmaxf(fmaf(a2.w, y3, b2.w), 0.f) * w4.w;
#pragma unroll
        for (int o = 8; o; o >>= 1) s += __shfl_xor_sync(0xffffffffu, s, o);
        if (q16 == 0) out[r] = s + ob;
    }
}

// ---------------- launch ----------------------------------------------------
extern "C" void kernel_launch(void* const* d_in, const int* in_sizes, int n_in,
                              void* d_out, int out_size) {
    const float* data     = (const float*)d_in[0];
    // d_in[1] = org_edge_index (int64) — unused by the reference
    const float* emb      = (const float*)d_in[2];
    const float* lin_w    = (const float*)d_in[3];
    const float* att_i    = (const float*)d_in[4];
    const float* att_j    = (const float*)d_in[5];
    const float* aei      = (const float*)d_in[6];
    const float* aej      = (const float*)d_in[7];
    const float* gnn_bias = (const float*)d_in[8];
    const float* g1       = (const float*)d_in[9];
    const float* b1       = (const float*)d_in[10];
    const float* g2       = (const float*)d_in[11];
    const float* b2       = (const float*)d_in[12];
    const float* out_w    = (const float*)d_in[13];
    const float* out_b    = (const float*)d_in[14];
    float* out = (float*)d_out;

    cudaFuncSetAttribute(k_main, cudaFuncAttributeMaxDynamicSharedMemorySize,
                         kN * 32 * (int)sizeof(float));

    k_fused1<<<768, 256>>>(emb, aei, aej, data, lin_w, att_i, att_j);
    k_topk<<<1024, 256>>>();
    k_main<<<128, 1024, kN * 32 * sizeof(float)>>>(gnn_bias);
    k_stats2<<<1024, 256>>>(emb, g1, b1);
    k_final<<<512, 256>>>(emb, out_w, out_b, g1, b1, g2, b2, out);
}

// round 17
// speedup vs baseline: 2.1293x; 1.1113x over previous
#include <cuda_runtime.h>
#include <math.h>

// Problem constants
constexpr int kB = 64, kN = 1024, kF = 16, kD = 64, kK = 20;
constexpr int kM = kB * kN;              // 65536 rows
constexpr float kEps = 1e-5f, kSlope = 0.2f;

// ---------------- scratch (device globals: allocation-free) ----------------
__device__ float  g_h[(size_t)kM * kD];      // 16 MB
__device__ float  g_out1[(size_t)kM * kD];   // 16 MB
__device__ float2 g_esi2[kM];                // {e^si, e^{0.2 si}}
__device__ float2 g_esj2[kM];                // {e^sj, e^{0.2 sj}}
__device__ float  g_cos[(size_t)kN * kN];    // 4 MB
__device__ int    g_idx[kN * kK];
__device__ double g_sum1[kD], g_ssq1[kD], g_sum2[kD], g_ssq2[kD];

// ---------------- kernel 1: FUSED cosine-Gram (blocks 0..255) +
//                  h/exp-tables (blocks 256..767) -----------------------------
__global__ void k_fused1(const float* __restrict__ emb,
                         const float* __restrict__ aei,
                         const float* __restrict__ aej,
                         const float* __restrict__ data,
                         const float* __restrict__ lin_w,
                         const float* __restrict__ att_i,
                         const float* __restrict__ att_j) {
    __shared__ float As[kD][68];   // cos part (row stride 272B, float4-aligned)
    __shared__ float Bs[kD][68];
    __shared__ float rnA[64], rnB[64];
    __shared__ float lw[kF][kD];   // h part
    int t = threadIdx.x;
    if (blockIdx.x < 256) {
        // ================= cos part =================
        int bn = (blockIdx.x >> 4) * 64, bm = (blockIdx.x & 15) * 64;
        if (blockIdx.x == 0 && t < kD) {
            g_sum1[t] = 0.0; g_ssq1[t] = 0.0; g_sum2[t] = 0.0; g_ssq2[t] = 0.0;
        }
        for (int idx = t; idx < 64 * 64; idx += 256) {
            int r = idx >> 6, k = idx & 63;
            As[k][r] = emb[(size_t)(bn + r) * kD + k];
            Bs[k][r] = emb[(size_t)(bm + r) * kD + k];
        }
        __syncthreads();
        if (t < 64) {
            float s = 0.f;
            for (int k = 0; k < 64; k++) { float v = As[k][t]; s += v * v; }
            rnA[t] = 1.0f / sqrtf(s);
        } else if (t < 128) {
            int r = t - 64;
            float s = 0.f;
            for (int k = 0; k < 64; k++) { float v = Bs[k][r]; s += v * v; }
            rnB[r] = 1.0f / sqrtf(s);
        }
        int tx = t & 15, ty = t >> 4;
        float acc[4][4] = {};
#pragma unroll 4
        for (int k = 0; k < 64; k++) {
            float4 a4 = *reinterpret_cast<const float4*>(&As[k][ty * 4]);
            float4 b4 = *reinterpret_cast<const float4*>(&Bs[k][tx * 4]);
            float a[4] = {a4.x, a4.y, a4.z, a4.w};
            float b[4] = {b4.x, b4.y, b4.z, b4.w};
#pragma unroll
            for (int i = 0; i < 4; i++)
#pragma unroll
                for (int j = 0; j < 4; j++) acc[i][j] += a[i] * b[j];
        }
        __syncthreads();
#pragma unroll
        for (int i = 0; i < 4; i++) {
            int r = bn + ty * 4 + i;
            float rn = rnA[ty * 4 + i];
#pragma unroll
            for (int j = 0; j < 4; j++) {
                int c = bm + tx * 4 + j;
                g_cos[(size_t)r * kN + c] = acc[i][j] * rn * rnB[tx * 4 + j];
            }
        }
    } else {
        // ================= h part =================
        for (int idx = t; idx < kF * kD; idx += 256) {
            int f = idx >> 6, d = idx & 63;
            lw[f][d] = lin_w[d * kF + f];
        }
        __syncthreads();
        int lane = t & 31, wid = t >> 5;
        int gw = (blockIdx.x - 256) * 8 + wid;          // 0..4095
        float ai0 = att_i[lane], ai1 = att_i[lane + 32];
        float aj0 = att_j[lane], aj1 = att_j[lane + 32];
        float ei0 = aei[lane],   ei1 = aei[lane + 32];
        float ej0 = aej[lane],   ej1 = aej[lane + 32];
        for (int r = gw; r < kM; r += 4096) {
            const float4* dp = reinterpret_cast<const float4*>(data + (size_t)r * kF);
            float4 q0 = dp[0], q1 = dp[1], q2 = dp[2], q3 = dp[3];
            float df[16] = {q0.x, q0.y, q0.z, q0.w, q1.x, q1.y, q1.z, q1.w,
                            q2.x, q2.y, q2.z, q2.w, q3.x, q3.y, q3.z, q3.w};
            float h0 = 0.f, h1 = 0.f;
#pragma unroll
            for (int f = 0; f < 16; f++) {
                h0 += df[f] * lw[f][lane];
                h1 += df[f] * lw[f][lane + 32];
            }
            g_h[(size_t)r * kD + lane] = h0;
            g_h[(size_t)r * kD + lane + 32] = h1;
            int n = r & (kN - 1);
            float e0 = emb[(size_t)n * kD + lane];
            float e1 = emb[(size_t)n * kD + lane + 32];
            float vi = h0 * ai0 + h1 * ai1 + e0 * ei0 + e1 * ei1;
            float vj = h0 * aj0 + h1 * aj1 + e0 * ej0 + e1 * ej1;
#pragma unroll
            for (int o = 16; o; o >>= 1) {
                vi += __shfl_xor_sync(0xffffffffu, vi, o);
                vj += __shfl_xor_sync(0xffffffffu, vj, o);
            }
            if (lane == 0) {
                g_esi2[r] = make_float2(expf(vi), expf(0.2f * vi));
                g_esj2[r] = make_float2(expf(vj), expf(0.2f * vj));
            }
        }
    }
}

// ---------------- kernel 2: top-20 radix select with candidate compaction ---
__global__ void k_topk() {
    __shared__ unsigned sv[kN];
    __shared__ int hist[256];
    __shared__ int suf[257];
    __shared__ unsigned cva[kN]; __shared__ int cia[kN];
    __shared__ unsigned cvb[kN]; __shared__ int cib[kN];
    __shared__ int s_digit, s_need, s_out, s_ca, s_cb, s_sel;
    __shared__ int wmin[8];
    int n = blockIdx.x, t = threadIdx.x;
    int lane = t & 31, wid = t >> 5;
    const uint4* row4 = reinterpret_cast<const uint4*>(g_cos + (size_t)n * kN);
    {
        uint4 x = row4[t];
        uint4 y;
        y.x = x.x ^ ((x.x & 0x80000000u) ? 0xFFFFFFFFu : 0x80000000u);
        y.y = x.y ^ ((x.y & 0x80000000u) ? 0xFFFFFFFFu : 0x80000000u);
        y.z = x.z ^ ((x.z & 0x80000000u) ? 0xFFFFFFFFu : 0x80000000u);
        y.w = x.w ^ ((x.w & 0x80000000u) ? 0xFFFFFFFFu : 0x80000000u);
        reinterpret_cast<uint4*>(sv)[t] = y;   // sv[4t..4t+3] = cols 4t..4t+3
    }
    hist[t] = 0;
    if (t == 0) { s_need = kK; s_out = 0; s_ca = 0; suf[256] = 0; }
    __syncthreads();
#pragma unroll
    for (int i = 0; i < 4; i++)
        atomicAdd(&hist[sv[t + 256 * i] >> 24], 1);
    __syncthreads();
    if (wid == 0) {  // suffix sums: suf[e] = count of digit >= e
        int base = 255 - 8 * lane;
        int loc[8], s = 0;
#pragma unroll
        for (int j = 0; j < 8; j++) { loc[j] = hist[base - j]; s += loc[j]; }
        int run = s;
#pragma unroll
        for (int off = 1; off < 32; off <<= 1) {
            int v = __shfl_up_sync(0xffffffffu, run, off);
            if (lane >= off) run += v;
        }
        int acc = run - s;
#pragma unroll
        for (int j = 0; j < 8; j++) { acc += loc[j]; suf[base - j] = acc; }
    }
    __syncthreads();
    {
        int need = s_need;
        if (suf[t] >= need && suf[t + 1] < need) s_digit = t;
    }
    __syncthreads();
    {
        int digit = s_digit;
        int above = suf[digit + 1];
#pragma unroll
        for (int i = 0; i < 4; i++) {
            int m = t + 256 * i;
            unsigned x = sv[m];
            int d = x >> 24;
            if (d > digit)       { int p = atomicAdd(&s_out, 1); g_idx[n * kK + p] = m; }
            else if (d == digit) { int p = atomicAdd(&s_ca, 1); cva[p] = x; cia[p] = m; }
        }
        if (t == 0) s_need = kK - above;
    }
    __syncthreads();
    unsigned* cv = cva; int* ci = cia;
    unsigned* nv = cvb; int* niv = cib;
    int C = s_ca;
    for (int shift = 16; shift >= 0; shift -= 8) {
        hist[t] = 0;
        if (t == 0) s_cb = 0;
        __syncthreads();
        for (int i = t; i < C; i += 256)
            atomicAdd(&hist[(cv[i] >> shift) & 255], 1);
        __syncthreads();
        if (wid == 0) {
            int base = 255 - 8 * lane;
            int loc[8], s = 0;
#pragma unroll
            for (int j = 0; j < 8; j++) { loc[j] = hist[base - j]; s += loc[j]; }
            int run = s;
#pragma unroll
            for (int off = 1; off < 32; off <<= 1) {
                int v = __shfl_up_sync(0xffffffffu, run, off);
                if (lane >= off) run += v;
            }
            int acc = run - s;
#pragma unroll
            for (int j = 0; j < 8; j++) { acc += loc[j]; suf[base - j] = acc; }
        }
        __syncthreads();
        int need = s_need;
        if (suf[t] >= need && suf[t + 1] < need) s_digit = t;
        __syncthreads();
        int digit = s_digit;
        int above = suf[digit + 1];
        for (int i = t; i < C; i += 256) {
            unsigned x = cv[i];
            int d = (x >> shift) & 255;
            if (d > digit)       { int p = atomicAdd(&s_out, 1); g_idx[n * kK + p] = ci[i]; }
            else if (d == digit) { int p = atomicAdd(&s_cb, 1); nv[p] = x; niv[p] = ci[i]; }
        }
        if (t == 0) s_need = need - above;
        __syncthreads();
        C = s_cb;
        unsigned* tv = cv; cv = nv; nv = tv;
        int* ti = ci; ci = niv; niv = ti;
    }
    int R = s_need;
    int base = kK - R;
    if (C == R) {
        if (t < R) g_idx[n * kK + base + t] = ci[t];
    } else {  // rare: multiplicity at threshold -> lowest indices win
        for (int r = 0; r < R; r++) {
            int best = 0x7fffffff;
            for (int i = t; i < C; i += 256) best = min(best, ci[i]);
#pragma unroll
            for (int o = 16; o; o >>= 1) best = min(best, __shfl_xor_sync(0xffffffffu, best, o));
            if (lane == 0) wmin[wid] = best;
            __syncthreads();
            if (t == 0) {
                int m = 0x7fffffff;
                for (int w = 0; w < 8; w++) m = min(m, wmin[w]);
                g_idx[n * kK + base + r] = m;
                s_sel = m;
            }
            __syncthreads();
            for (int i = t; i < C; i += 256) if (ci[i] == s_sel) ci[i] = 0x7fffffff;
            __syncthreads();
        }
    }
}

// ---------------- kernel 3: inline alpha + smem gather + BN1 stats ----------
__global__ void __launch_bounds__(1024, 1)
k_main(const float* __restrict__ gnn_bias) {
    extern __shared__ float sh[];              // [1024][32] = 128 KB
    __shared__ float4 sp4[32][40];             // 20 KB
    __shared__ float  rs[32][32], rq[32][32];  // 8 KB
    __shared__ float2 ssi[kN], ssj[kN];        // 16 KB
    int t = threadIdx.x, lane = t & 31, wid = t >> 5;
    int sub = lane >> 3, li = lane & 7;
    int b = blockIdx.x >> 1, half = blockIdx.x & 1;
    const float4* hb4 = reinterpret_cast<const float4*>(
        g_h + (size_t)b * kN * kD + half * 32);
    float4* sh4w = reinterpret_cast<float4*>(sh);
    for (int i = t; i < kN * 8; i += 1024) {   // 8192 float4 = 128 KB
        int n = i >> 3, j = i & 7;
        sh4w[i] = hb4[n * 16 + j];
    }
    for (int i = t; i < kN; i += 1024) {
        ssi[i] = g_esi2[b * kN + i];
        ssj[i] = g_esj2[b * kN + i];
    }
    __syncthreads();
    const float4* sh4 = reinterpret_cast<const float4*>(sh);
    const int2* idx2 = reinterpret_cast<const int2*>(g_idx);   // 10 int2 per row
    float4 bias4 = reinterpret_cast<const float4*>(gnn_bias)[half * 8 + li];
    float4 ts4 = make_float4(0.f, 0.f, 0.f, 0.f);
    float4 tq4 = make_float4(0.f, 0.f, 0.f, 0.f);
#pragma unroll 1
    for (int g = 0; g < 8; g++) {
        int n0 = (g * 32 + wid) * 4;
#pragma unroll
        for (int pass = 0; pass < 2; pass++) {
            int idx = lane + pass * 32;
            if (idx < 40) {
                int r = idx / 10, j = idx - r * 10;
                int n = n0 + r;
                int2 ids = idx2[n * 10 + j];
                float2 ei = ssi[n];
                float2 e0 = ssj[ids.x], e1 = ssj[ids.y];
                float f0 = ei.x * e0.x, f1 = ei.x * e1.x;
                float w0 = (f0 > 1.f) ? f0 : ei.y * e0.y;
                float w1 = (f1 > 1.f) ? f1 : ei.y * e1.y;
                sp4[wid][idx] = make_float4(w0, __int_as_float(ids.x),
                                            w1, __int_as_float(ids.y));
            }
        }
        __syncwarp();
        float4 accA = make_float4(0.f, 0.f, 0.f, 0.f);
        float4 accB = make_float4(0.f, 0.f, 0.f, 0.f);
        float dnA = 0.f, dnB = 0.f;
#pragma unroll
        for (int k2 = 0; k2 < kK / 2; k2 += 2) {
            float4 p = sp4[wid][sub * 10 + k2];       // (e0,id0,e1,id1)
            float4 q = sp4[wid][sub * 10 + k2 + 1];
            float4 v0 = sh4[__float_as_int(p.y) * 8 + li];
            float4 v1 = sh4[__float_as_int(p.w) * 8 + li];
            float4 u0 = sh4[__float_as_int(q.y) * 8 + li];
            float4 u1 = sh4[__float_as_int(q.w) * 8 + li];
            dnA += p.x + p.z;
            dnB += q.x + q.z;
            accA.x = fmaf(p.x, v0.x, fmaf(p.z, v1.x, accA.x));
            accA.y = fmaf(p.x, v0.y, fmaf(p.z, v1.y, accA.y));
            accA.z = fmaf(p.x, v0.z, fmaf(p.z, v1.z, accA.z));
            accA.w = fmaf(p.x, v0.w, fmaf(p.z, v1.w, accA.w));
            accB.x = fmaf(q.x, u0.x, fmaf(q.z, u1.x, accB.x));
            accB.y = fmaf(q.x, u0.y, fmaf(q.z, u1.y, accB.y));
            accB.z = fmaf(q.x, u0.z, fmaf(q.z, u1.z, accB.z));
            accB.w = fmaf(q.x, u0.w, fmaf(q.z, u1.w, accB.w));
        }
        float inv = 1.0f / (dnA + dnB);
        float4 o4;
        o4.x = fmaf(accA.x + accB.x, inv, bias4.x);
        o4.y = fmaf(accA.y + accB.y, inv, bias4.y);
        o4.z = fmaf(accA.z + accB.z, inv, bias4.z);
        o4.w = fmaf(accA.w + accB.w, inv, bias4.w);
        reinterpret_cast<float4*>(
            g_out1 + ((size_t)b * kN + n0 + sub) * kD + half * 32)[li] = o4;
        ts4.x += o4.x; ts4.y += o4.y; ts4.z += o4.z; ts4.w += o4.w;
        tq4.x = fmaf(o4.x, o4.x, tq4.x); tq4.y = fmaf(o4.y, o4.y, tq4.y);
        tq4.z = fmaf(o4.z, o4.z, tq4.z); tq4.w = fmaf(o4.w, o4.w, tq4.w);
        __syncwarp();                          // WAR on sp4[wid]
    }
#pragma unroll
    for (int off = 8; off <= 16; off <<= 1) {
        ts4.x += __shfl_xor_sync(0xffffffffu, ts4.x, off);
        ts4.y += __shfl_xor_sync(0xffffffffu, ts4.y, off);
        ts4.z += __shfl_xor_sync(0xffffffffu, ts4.z, off);
        ts4.w += __shfl_xor_sync(0xffffffffu, ts4.w, off);
        tq4.x += __shfl_xor_sync(0xffffffffu, tq4.x, off);
        tq4.y += __shfl_xor_sync(0xffffffffu, tq4.y, off);
        tq4.z += __shfl_xor_sync(0xffffffffu, tq4.z, off);
        tq4.w += __shfl_xor_sync(0xffffffffu, tq4.w, off);
    }
    if (sub == 0) {
        reinterpret_cast<float4*>(&rs[wid][0])[li] = ts4;
        reinterpret_cast<float4*>(&rq[wid][0])[li] = tq4;
    }
    __syncthreads();
    if (t < 32) {
        float s = 0.f, q = 0.f;
#pragma unroll 8
        for (int w = 0; w < 32; w++) { s += rs[w][t]; q += rq[w][t]; }
        atomicAdd(&g_sum1[half * 32 + t], (double)s);
        atomicAdd(&g_ssq1[half * 32 + t], (double)q);
    }
}

// ---------------- BN affine finalize (block-level; fp64 amortized) ----------
__device__ __forceinline__ void bn_ab(int d, const float* gm, const float* bt,
                                      const double* S, const double* Q,
                                      float& a, float& b) {
    double m = S[d] / (double)kM;
    double var = Q[d] / (double)kM - m * m;
    float inv = (float)(1.0 / sqrt(var + (double)kEps));
    a = gm[d] * inv;
    b = bt[d] - (float)m * a;
}

// ---------------- kernel 4: BN2 statistics (128 blocks: short atomic chains) -
__global__ void k_stats2(const float* __restrict__ emb,
                         const float* __restrict__ g1, const float* __restrict__ b1v) {
    __shared__ float a1s[kD], b1s[kD];
    __shared__ float4 rs[16][16], rq[16][16];
    int t = threadIdx.x;
    if (t < kD) { float a, b; bn_ab(t, g1, b1v, g_sum1, g_ssq1, a, b); a1s[t] = a; b1s[t] = b; }
    __syncthreads();
    int q16 = t & 15, rg = t >> 4;
    float4 a1 = *reinterpret_cast<const float4*>(&a1s[q16 * 4]);
    float4 b1 = *reinterpret_cast<const float4*>(&b1s[q16 * 4]);
    const float4* o14 = reinterpret_cast<const float4*>(g_out1);
    const float4* em4 = reinterpret_cast<const float4*>(emb);
    float4 ts = make_float4(0.f, 0.f, 0.f, 0.f);
    float4 tq = make_float4(0.f, 0.f, 0.f, 0.f);
    int r0 = blockIdx.x * 512;               // 512 rows per block
#pragma unroll 4
    for (int i = 0; i < 32; i++) {
        int r = r0 + i * 16 + rg;
        float4 x = o14[(size_t)r * 16 + q16];
        float4 e = em4[(size_t)(r & (kN - 1)) * 16 + q16];
        float y0 = fmaxf(fmaf(a1.x, x.x, b1.x), 0.f) * e.x;
        float y1 = fmaxf(fmaf(a1.y, x.y, b1.y), 0.f) * e.y;
        float y2 = fmaxf(fmaf(a1.z, x.z, b1.z), 0.f) * e.z;
        float y3 = fmaxf(fmaf(a1.w, x.w, b1.w), 0.f) * e.w;
        ts.x += y0; ts.y += y1; ts.z += y2; ts.w += y3;
        tq.x = fmaf(y0, y0, tq.x); tq.y = fmaf(y1, y1, tq.y);
        tq.z = fmaf(y2, y2, tq.z); tq.w = fmaf(y3, y3, tq.w);
    }
    rs[rg][q16] = ts; rq[rg][q16] = tq;
    __syncthreads();
    if (t < kD) {
        int c4 = t >> 2, cc = t & 3;
        float s = 0.f, q = 0.f;
#pragma unroll
        for (int g = 0; g < 16; g++) {
            const float* pr = reinterpret_cast<const float*>(&rs[g][c4]);
            const float* pq = reinterpret_cast<const float*>(&rq[g][c4]);
            s += pr[cc]; q += pq[cc];
        }
        atomicAdd(&g_sum2[t], (double)s);
        atomicAdd(&g_ssq2[t], (double)q);
    }
}

// ---------------- kernel 5: final projection (half-warp per row, float4) ----
__global__ void k_final(const float* __restrict__ emb, const float* __restrict__ out_w,
                        const float* __restrict__ out_b,
                        const float* __restrict__ g1, const float* __restrict__ b1v,
                        const float* __restrict__ g2, const float* __restrict__ b2v,
                        float* __restrict__ out) {
    __shared__ float aff[4][kD];
    __shared__ float ws[kD];
    int t = threadIdx.x, lane = t & 31;
    if (t < kD) {
        float a, b;
        bn_ab(t, g1, b1v, g_sum1, g_ssq1, a, b); aff[0][t] = a; aff[1][t] = b;
        bn_ab(t, g2, b2v, g_sum2, g_ssq2, a, b); aff[2][t] = a; aff[3][t] = b;
        ws[t] = out_w[t];
    }
    __syncthreads();
    int h = lane >> 4, q16 = lane & 15;
    float4 a1 = *reinterpret_cast<const float4*>(&aff[0][q16 * 4]);
    float4 b1 = *reinterpret_cast<const float4*>(&aff[1][q16 * 4]);
    float4 a2 = *reinterpret_cast<const float4*>(&aff[2][q16 * 4]);
    float4 b2 = *reinterpret_cast<const float4*>(&aff[3][q16 * 4]);
    float4 w4 = *reinterpret_cast<const float4*>(&ws[q16 * 4]);
    float ob = out_b[0];
    const float4* o14 = reinterpret_cast<const float4*>(g_out1);
    const float4* em4 = reinterpret_cast<const float4*>(emb);
    int gw = (blockIdx.x * blockDim.x + t) >> 5;
    int nw = (gridDim.x * blockDim.x) >> 5;
    for (int rp = gw; rp < kM / 2; rp += nw) {
        int r = rp * 2 + h;
        int n = r & (kN - 1);
        float4 x = o14[(size_t)r * 16 + q16];
        float4 e = em4[(size_t)n * 16 + q16];
        float y0 = fmaxf(fmaf(a1.x, x.x, b1.x), 0.f) * e.x;
        float y1 = fmaxf(fmaf(a1.y, x.y, b1.y), 0.f) * e.y;
        float y2 = fmaxf(fmaf(a1.z, x.z, b1.z), 0.f) * e.z;
        float y3 = fmaxf(fmaf(a1.w, x.w, b1.w), 0.f) * e.w;
        float s = fmaxf(fmaf(a2.x, y0, b2.x), 0.f) * w4.x
                + fmaxf(fmaf(a2.y, y1, b2.y), 0.f) * w4.y
                + fmaxf(fmaf(a2.z, y2, b2.z), 0.f) * w4.z
                + fmaxf(fmaf(a2.w, y3, b2.w), 0.f) * w4.w;
#pragma unroll
        for (int o = 8; o; o >>= 1) s += __shfl_xor_sync(0xffffffffu, s, o);
        if (q16 == 0) out[r] = s + ob;
    }
}

// ---------------- launch ----------------------------------------------------
extern "C" void kernel_launch(void* const* d_in, const int* in_sizes, int n_in,
                              void* d_out, int out_size) {
    const float* data     = (const float*)d_in[0];
    // d_in[1] = org_edge_index (int64) — unused by the reference
    const float* emb      = (const float*)d_in[2];
    const float* lin_w    = (const float*)d_in[3];
    const float* att_i    = (const float*)d_in[4];
    const float* att_j    = (const float*)d_in[5];
    const float* aei      = (const float*)d_in[6];
    const float* aej      = (const float*)d_in[7];
    const float* gnn_bias = (const float*)d_in[8];
    const float* g1       = (const float*)d_in[9];
    const float* b1       = (const float*)d_in[10];
    const float* g2       = (const float*)d_in[11];
    const float* b2       = (const float*)d_in[12];
    const float* out_w    = (const float*)d_in[13];
    const float* out_b    = (const float*)d_in[14];
    float* out = (float*)d_out;

    cudaFuncSetAttribute(k_main, cudaFuncAttributeMaxDynamicSharedMemorySize,
                         kN * 32 * (int)sizeof(float));

    k_fused1<<<768, 256>>>(emb, aei, aej, data, lin_w, att_i, att_j);
    k_topk<<<1024, 256>>>();
    k_main<<<128, 1024, kN * 32 * sizeof(float)>>>(gnn_bias);
    k_stats2<<<128, 256>>>(emb, g1, b1);
    k_final<<<512, 256>>>(emb, out_w, out_b, g1, b1, g2, b2, out);
}